// round 13
// baseline (speedup 1.0000x reference)
#include <cuda_runtime.h>
#include <cuda_fp16.h>
#include <cstdint>

// HGCN (math-reduced), fp16 mma.sync, both GCN layers fused:
//   kPrep : W01h=half(We@W0z); W1zh/Wozh=half(row0-zeroed W1/W_out)  [k][n]
//   kRowH : S0 = half(x @ W01 + b0)                     (row-major half, gmem)
//   kFuse : per batch b (one CTA):
//             adjh  = half(adj_b)            (SMEM-resident, streamed once)
//             T1    = half(relu(adjh@S0/100));  S1 = half(T1@W1z + b1)  (SMEM)
//             T2    = half(relu(adjh@S1/100));  out = (T2@Woz + b_out)*mask
// m16n8k16 HMMA fp32-accum; A via ldmatrix.x4 (64B swizzled rows), B/W/T via
// ldmatrix.x4.trans (144B pitch).

static constexpr int NP = 256, HD = 64;

__device__ __half   g_bufA[131072 * 64];     // S0
__device__ uint16_t g_WpreH[3 * 4096];

// ---- kFuse smem (bytes), total 223744 --------------------------------------
static constexpr int FZ_ADJ = 0;        // 8 chunks x 16384 (256 rows x 64B, swizzled)
static constexpr int FZ_B   = 131072;   // S0 stream: 2 x 4608 (32 rows x 144B)
static constexpr int FZ_WO  = 131072;   // Wo tile (9216) overlays FZ_B after loop1
static constexpr int FZ_S1  = 140288;   // 256 x 144B = 36864
static constexpr int FZ_T   = 177152;   // T tile 36864; fp32 stage (32768) overlays
static constexpr int FZ_W   = 214016;   // W1 tile 64 x 144B = 9216
static constexpr int FZ_BYTES = 223744;
// ---- kRowH smem ------------------------------------------------------------
static constexpr int KR_ST   = 0;
static constexpr int KR_XH   = 32768;
static constexpr int KR_W    = 51200;
static constexpr int KR_BIAS = 60416;
static constexpr int KR_BYTES= 60672;

// ---- helpers ---------------------------------------------------------------
__device__ __forceinline__ uint32_t smem_u32(const void* p) {
    uint32_t a;
    asm("{ .reg .u64 t; cvta.to.shared.u64 t, %1; cvt.u32.u64 %0, t; }"
        : "=r"(a) : "l"(p));
    return a;
}
__device__ __forceinline__ void cpa16(uint32_t dst, const void* src) {
    asm volatile("cp.async.ca.shared.global [%0], [%1], 16;\n"
                 :: "r"(dst), "l"(src));
}
__device__ __forceinline__ void ldsm4(uint32_t* r, uint32_t addr) {
    asm volatile("ldmatrix.sync.aligned.m8n8.x4.shared.b16 {%0,%1,%2,%3}, [%4];"
                 : "=r"(r[0]), "=r"(r[1]), "=r"(r[2]), "=r"(r[3]) : "r"(addr));
}
__device__ __forceinline__ void ldsm4t(uint32_t* r, uint32_t addr) {
    asm volatile("ldmatrix.sync.aligned.m8n8.x4.trans.shared.b16 {%0,%1,%2,%3}, [%4];"
                 : "=r"(r[0]), "=r"(r[1]), "=r"(r[2]), "=r"(r[3]) : "r"(addr));
}
__device__ __forceinline__ void mma16(float* c, const uint32_t* a,
                                      uint32_t b0, uint32_t b1) {
    asm volatile(
        "mma.sync.aligned.m16n8k16.row.col.f32.f16.f16.f32 "
        "{%0,%1,%2,%3}, {%4,%5,%6,%7}, {%8,%9}, {%0,%1,%2,%3};\n"
        : "+f"(c[0]), "+f"(c[1]), "+f"(c[2]), "+f"(c[3])
        : "r"(a[0]), "r"(a[1]), "r"(a[2]), "r"(a[3]), "r"(b0), "r"(b1));
}
__device__ __forceinline__ uint32_t pk2h(float a, float b) {
    __half2 h = __floats2half2_rn(a, b);
    return *reinterpret_cast<uint32_t*>(&h);
}
// A-tile swizzle: 64B rows, 16B units; unit' = q ^ ((r>>1)&3)
__device__ __forceinline__ int aswz(int r, int q) {
    return r * 64 + ((q ^ ((r >> 1) & 3)) << 4);
}

// ---------------------------------------------------------------------------
__global__ void __launch_bounds__(256)
kPrep(const float* __restrict__ We, const float* __restrict__ W0,
      const float* __restrict__ W1, const float* __restrict__ Wo,
      uint16_t* __restrict__ WpreH) {
    int id = blockIdx.x * 256 + threadIdx.x;
    int which = id >> 12;
    int li = id & 4095;
    int k = li >> 6, n = li & 63;
    float v;
    if (which == 0) {
        float s = 0.f;
        #pragma unroll 8
        for (int kk = 1; kk < 64; kk++) s += We[k * 64 + kk] * W0[kk * 64 + n];
        v = s;
    } else {
        const float* W = (which == 1) ? W1 : Wo;
        v = (k == 0) ? 0.f : W[li];
    }
    __half h = __float2half_rn(v);
    WpreH[id] = *reinterpret_cast<uint16_t*>(&h);
}

// ---------------------------------------------------------------------------
// kRowH (unchanged, passing since R9): S0 = half(x @ W01 + b0)
// ---------------------------------------------------------------------------
__global__ void __launch_bounds__(256, 2)
kRowH(const float* __restrict__ X, const uint16_t* __restrict__ Wh,
      const float* __restrict__ bias, __half* __restrict__ S) {
    extern __shared__ char sm[];
    const uint32_t sb = smem_u32(sm);
    const int tid = threadIdx.x;
    const int lane = tid & 31, w = tid >> 5;
    const int g = lane >> 2;
    const int wm = w & 3, wn = w >> 2;
    const long row0 = (long)blockIdx.x * 128;

    #pragma unroll
    for (int i = 0; i < 8; i++) {
        int u = tid + i * 256;
        cpa16(sb + KR_ST + u * 16, X + (row0 + (u >> 4)) * 64 + (u & 15) * 4);
    }
    #pragma unroll
    for (int i = 0; i < 2; i++) {
        int u = tid + i * 256;
        cpa16(sb + KR_W + (u >> 3) * 144 + (u & 7) * 16,
              Wh + (u >> 3) * 64 + (u & 7) * 8);
    }
    asm volatile("cp.async.commit_group;\n");
    if (tid < HD) *reinterpret_cast<float*>(sm + KR_BIAS + tid * 4) = bias[tid];
    asm volatile("cp.async.wait_group 0;\n");
    __syncthreads();

    #pragma unroll
    for (int i = 0; i < 8; i++) {
        int u = tid + i * 256;
        int r = u >> 4, q = u & 15;
        float4 v = *reinterpret_cast<float4*>(sm + KR_ST + u * 16);
        uint2 h;
        h.x = pk2h(v.x, v.y);
        h.y = pk2h(v.z, v.w);
        *reinterpret_cast<uint2*>(sm + KR_XH + r * 144 + q * 8) = h;
    }
    __syncthreads();

    float acc[2][4][4];
    #pragma unroll
    for (int i = 0; i < 2; i++)
        #pragma unroll
        for (int j = 0; j < 4; j++)
            #pragma unroll
            for (int r = 0; r < 4; r++) acc[i][j][r] = 0.f;

    #pragma unroll
    for (int ks = 0; ks < 4; ks++) {
        uint32_t a[2][4], bb[2][4];
        #pragma unroll
        for (int i = 0; i < 2; i++)
            ldsm4(a[i], sb + KR_XH + (wm * 32 + i * 16 + (lane & 15)) * 144
                        + ks * 32 + (lane >> 4) * 16);
        #pragma unroll
        for (int p = 0; p < 2; p++)
            ldsm4t(bb[p], sb + KR_W + (ks * 16 + (lane & 15)) * 144
                          + (wn * 32 + p * 16 + (lane >> 4) * 8) * 2);
        #pragma unroll
        for (int j = 0; j < 4; j++) {
            uint32_t b0 = bb[j >> 1][(j & 1) * 2];
            uint32_t b1 = bb[j >> 1][(j & 1) * 2 + 1];
            mma16(acc[0][j], a[0], b0, b1);
            mma16(acc[1][j], a[1], b0, b1);
        }
    }

    const float* bsm = reinterpret_cast<const float*>(sm + KR_BIAS);
    #pragma unroll
    for (int i = 0; i < 2; i++)
        #pragma unroll
        for (int j = 0; j < 4; j++) {
            int col = wn * 32 + j * 8 + 2 * (lane & 3);
            float b0 = bsm[col], b1 = bsm[col + 1];
            int r0 = wm * 32 + i * 16 + g;
            uint32_t h0 = pk2h(acc[i][j][0] + b0, acc[i][j][1] + b1);
            uint32_t h1 = pk2h(acc[i][j][2] + b0, acc[i][j][3] + b1);
            *reinterpret_cast<uint32_t*>(S + (row0 + r0) * 64 + col)     = h0;
            *reinterpret_cast<uint32_t*>(S + (row0 + r0 + 8) * 64 + col) = h1;
        }
}

// ---------------------------------------------------------------------------
// kFuse: one CTA per batch; both GCN layers; adj read once (fp32), resident
// in SMEM as half for both mainloops. Layer-2 mainloop = pure SMEM compute.
// ---------------------------------------------------------------------------
__global__ void __launch_bounds__(256, 1)
kFuse(const float* __restrict__ adj, const __half* __restrict__ S0,
      const uint16_t* __restrict__ W1h, const uint16_t* __restrict__ Woh,
      const float* __restrict__ b1, const float* __restrict__ bo,
      const float* __restrict__ nmask, float* __restrict__ out) {
    extern __shared__ char sm[];
    const uint32_t sb = smem_u32(sm);
    const int tid = threadIdx.x;
    const int lane = tid & 31, w = tid >> 5;
    const int g = lane >> 2, t = lane & 3;
    const int wm = w & 3, wn = w >> 2;        // warp tile m64 x n32
    const int b = blockIdx.x;

    const float*  adjb = adj + (size_t)b * NP * NP;
    const __half* S0b  = S0 + (size_t)b * NP * HD;

    // prologue: group0 = W1 tile; group1 = adj chunk0 stage + S0 chunk0
    #pragma unroll
    for (int i = 0; i < 2; i++) {
        int u = tid + i * 256;
        cpa16(sb + FZ_W + (u >> 3) * 144 + (u & 7) * 16,
              W1h + (u >> 3) * 64 + (u & 7) * 8);
    }
    asm volatile("cp.async.commit_group;\n");
    #pragma unroll
    for (int i = 0; i < 8; i++) {
        int u = tid + i * 256;
        cpa16(sb + FZ_T + u * 16, adjb + (size_t)(u >> 3) * NP + (u & 7) * 4);
    }
    cpa16(sb + FZ_B + (tid >> 3) * 144 + (tid & 7) * 16,
          S0b + (size_t)(tid >> 3) * HD + (tid & 7) * 8);
    asm volatile("cp.async.commit_group;\n");

    float acc[4][4][4];
    #pragma unroll
    for (int i = 0; i < 4; i++)
        #pragma unroll
        for (int j = 0; j < 4; j++)
            #pragma unroll
            for (int r = 0; r < 4; r++) acc[i][j][r] = 0.f;

    // ---- layer-1 mainloop: stream adj once, build resident adjh chunks ----
    for (int c = 0; c < 8; c++) {
        asm volatile("cp.async.wait_group 0;\n");
        __syncthreads();                      // stage(c) + S0buf(c&1) visible

        // convert fp32 stage -> resident half chunk c (swizzled 64B rows)
        const int AH = FZ_ADJ + c * 16384;
        #pragma unroll
        for (int i = 0; i < 8; i++) {
            int u = tid + i * 256;
            int r = u >> 3, q32 = u & 7;
            float4 v = *reinterpret_cast<float4*>(sm + FZ_T + u * 16);
            uint2 h;
            h.x = pk2h(v.x, v.y);
            h.y = pk2h(v.z, v.w);
            *reinterpret_cast<uint2*>(sm + AH + aswz(r, q32 >> 1) + (q32 & 1) * 8) = h;
        }
        __syncthreads();                      // stage consumed; chunk c visible

        if (c + 1 < 8) {                      // refill stage + next S0 chunk
            #pragma unroll
            for (int i = 0; i < 8; i++) {
                int u = tid + i * 256;
                cpa16(sb + FZ_T + u * 16,
                      adjb + (size_t)(u >> 3) * NP + (c + 1) * 32 + (u & 7) * 4);
            }
            cpa16(sb + FZ_B + ((c + 1) & 1) * 4608 + (tid >> 3) * 144 + (tid & 7) * 16,
                  S0b + (size_t)((c + 1) * 32 + (tid >> 3)) * HD + (tid & 7) * 8);
            asm volatile("cp.async.commit_group;\n");
        }

        const int BH = FZ_B + (c & 1) * 4608;
        #pragma unroll
        for (int s = 0; s < 2; s++) {
            uint32_t a[4][4], bb[2][4];
            #pragma unroll
            for (int i = 0; i < 4; i++) {
                int r = wm * 64 + i * 16 + (lane & 15);
                ldsm4(a[i], sb + AH + aswz(r, 2 * s + (lane >> 4)));
            }
            #pragma unroll
            for (int p = 0; p < 2; p++)
                ldsm4t(bb[p], sb + BH + (s * 16 + (lane & 15)) * 144
                              + (wn * 32 + p * 16 + (lane >> 4) * 8) * 2);
            #pragma unroll
            for (int j = 0; j < 4; j++) {
                uint32_t b0 = bb[j >> 1][(j & 1) * 2];
                uint32_t b1 = bb[j >> 1][(j & 1) * 2 + 1];
                #pragma unroll
                for (int i = 0; i < 4; i++) mma16(acc[i][j], a[i], b0, b1);
            }
        }
    }

    __syncthreads();                          // loop1 done; stage & S0buf dead

    // Wo tile into dead S0-stream region (overlaps epilogue-1 + GEMM-2)
    #pragma unroll
    for (int i = 0; i < 2; i++) {
        int u = tid + i * 256;
        cpa16(sb + FZ_WO + (u >> 3) * 144 + (u & 7) * 16,
              Woh + (u >> 3) * 64 + (u & 7) * 8);
    }
    asm volatile("cp.async.commit_group;\n");

    // epilogue-1: T1 = half(relu(acc/100)) -> FZ_T
    #pragma unroll
    for (int i = 0; i < 4; i++)
        #pragma unroll
        for (int j = 0; j < 4; j++) {
            int r0 = wm * 64 + i * 16 + g;
            int col = wn * 32 + j * 8 + 2 * t;
            uint32_t h0 = pk2h(fmaxf(acc[i][j][0] * 0.01f, 0.f),
                               fmaxf(acc[i][j][1] * 0.01f, 0.f));
            uint32_t h1 = pk2h(fmaxf(acc[i][j][2] * 0.01f, 0.f),
                               fmaxf(acc[i][j][3] * 0.01f, 0.f));
            *reinterpret_cast<uint32_t*>(sm + FZ_T + r0 * 144 + col * 2)       = h0;
            *reinterpret_cast<uint32_t*>(sm + FZ_T + (r0 + 8) * 144 + col * 2) = h1;
        }
    __syncthreads();

    // GEMM-2: S1 = half(T1 @ W1z + b1) -> FZ_S1 (B-format)
    #pragma unroll
    for (int i = 0; i < 4; i++)
        #pragma unroll
        for (int j = 0; j < 4; j++)
            #pragma unroll
            for (int r = 0; r < 4; r++) acc[i][j][r] = 0.f;
    #pragma unroll
    for (int ks = 0; ks < 4; ks++) {
        uint32_t a[4][4], bb[2][4];
        #pragma unroll
        for (int i = 0; i < 4; i++)
            ldsm4(a[i], sb + FZ_T + (wm * 64 + i * 16 + (lane & 15)) * 144
                        + ks * 32 + (lane >> 4) * 16);
        #pragma unroll
        for (int p = 0; p < 2; p++)
            ldsm4t(bb[p], sb + FZ_W + (ks * 16 + (lane & 15)) * 144
                          + (wn * 32 + p * 16 + (lane >> 4) * 8) * 2);
        #pragma unroll
        for (int j = 0; j < 4; j++) {
            uint32_t b0 = bb[j >> 1][(j & 1) * 2];
            uint32_t b1 = bb[j >> 1][(j & 1) * 2 + 1];
            #pragma unroll
            for (int i = 0; i < 4; i++) mma16(acc[i][j], a[i], b0, b1);
        }
    }
    #pragma unroll
    for (int j = 0; j < 4; j++) {
        int col = wn * 32 + j * 8 + 2 * t;
        float v0 = b1[col], v1 = b1[col + 1];
        #pragma unroll
        for (int i = 0; i < 4; i++) {
            int r0 = wm * 64 + i * 16 + g;
            uint32_t h0 = pk2h(acc[i][j][0] + v0, acc[i][j][1] + v1);
            uint32_t h1 = pk2h(acc[i][j][2] + v0, acc[i][j][3] + v1);
            *reinterpret_cast<uint32_t*>(sm + FZ_S1 + r0 * 144 + col * 2)       = h0;
            *reinterpret_cast<uint32_t*>(sm + FZ_S1 + (r0 + 8) * 144 + col * 2) = h1;
        }
    }
    __syncthreads();                          // S1 visible

    // ---- layer-2 mainloop: adjh (resident) @ S1 (resident) — no syncs ----
    #pragma unroll
    for (int i = 0; i < 4; i++)
        #pragma unroll
        for (int j = 0; j < 4; j++)
            #pragma unroll
            for (int r = 0; r < 4; r++) acc[i][j][r] = 0.f;
    for (int c = 0; c < 8; c++) {
        const int AH = FZ_ADJ + c * 16384;
        #pragma unroll
        for (int s = 0; s < 2; s++) {
            uint32_t a[4][4], bb[2][4];
            #pragma unroll
            for (int i = 0; i < 4; i++) {
                int r = wm * 64 + i * 16 + (lane & 15);
                ldsm4(a[i], sb + AH + aswz(r, 2 * s + (lane >> 4)));
            }
            #pragma unroll
            for (int p = 0; p < 2; p++)
                ldsm4t(bb[p], sb + FZ_S1 + (c * 32 + s * 16 + (lane & 15)) * 144
                              + (wn * 32 + p * 16 + (lane >> 4) * 8) * 2);
            #pragma unroll
            for (int j = 0; j < 4; j++) {
                uint32_t b0 = bb[j >> 1][(j & 1) * 2];
                uint32_t b1 = bb[j >> 1][(j & 1) * 2 + 1];
                #pragma unroll
                for (int i = 0; i < 4; i++) mma16(acc[i][j], a[i], b0, b1);
            }
        }
    }
    __syncthreads();                          // T1 reads done -> T2 overlay

    // epilogue-2: T2 = half(relu(acc/100)) -> FZ_T
    #pragma unroll
    for (int i = 0; i < 4; i++)
        #pragma unroll
        for (int j = 0; j < 4; j++) {
            int r0 = wm * 64 + i * 16 + g;
            int col = wn * 32 + j * 8 + 2 * t;
            uint32_t h0 = pk2h(fmaxf(acc[i][j][0] * 0.01f, 0.f),
                               fmaxf(acc[i][j][1] * 0.01f, 0.f));
            uint32_t h1 = pk2h(fmaxf(acc[i][j][2] * 0.01f, 0.f),
                               fmaxf(acc[i][j][3] * 0.01f, 0.f));
            *reinterpret_cast<uint32_t*>(sm + FZ_T + r0 * 144 + col * 2)       = h0;
            *reinterpret_cast<uint32_t*>(sm + FZ_T + (r0 + 8) * 144 + col * 2) = h1;
        }
    asm volatile("cp.async.wait_group 0;\n"); // Wo resident
    __syncthreads();

    // GEMM-3: out = (T2 @ Woz + b_out) * mask  (fp32)
    #pragma unroll
    for (int i = 0; i < 4; i++)
        #pragma unroll
        for (int j = 0; j < 4; j++)
            #pragma unroll
            for (int r = 0; r < 4; r++) acc[i][j][r] = 0.f;
    #pragma unroll
    for (int ks = 0; ks < 4; ks++) {
        uint32_t a[4][4], bb[2][4];
        #pragma unroll
        for (int i = 0; i < 4; i++)
            ldsm4(a[i], sb + FZ_T + (wm * 64 + i * 16 + (lane & 15)) * 144
                        + ks * 32 + (lane >> 4) * 16);
        #pragma unroll
        for (int p = 0; p < 2; p++)
            ldsm4t(bb[p], sb + FZ_WO + (ks * 16 + (lane & 15)) * 144
                          + (wn * 32 + p * 16 + (lane >> 4) * 8) * 2);
        #pragma unroll
        for (int j = 0; j < 4; j++) {
            uint32_t b0 = bb[j >> 1][(j & 1) * 2];
            uint32_t b1 = bb[j >> 1][(j & 1) * 2 + 1];
            #pragma unroll
            for (int i = 0; i < 4; i++) mma16(acc[i][j], a[i], b0, b1);
        }
    }

    const float* mrow = nmask + (size_t)b * NP;
    #pragma unroll
    for (int j = 0; j < 4; j++) {
        int col = wn * 32 + j * 8 + 2 * t;
        float v0 = bo[col], v1 = bo[col + 1];
        #pragma unroll
        for (int i = 0; i < 4; i++) {
            int r0 = wm * 64 + i * 16 + g;
            float m0 = mrow[r0], m1 = mrow[r0 + 8];
            float2 o0, o1;
            o0.x = (acc[i][j][0] + v0) * m0;
            o0.y = (acc[i][j][1] + v1) * m0;
            o1.x = (acc[i][j][2] + v0) * m1;
            o1.y = (acc[i][j][3] + v1) * m1;
            *reinterpret_cast<float2*>(out + ((size_t)b * NP + r0) * HD + col)     = o0;
            *reinterpret_cast<float2*>(out + ((size_t)b * NP + r0 + 8) * HD + col) = o1;
        }
    }
}

// ---------------------------------------------------------------------------
extern "C" void kernel_launch(void* const* d_in, const int* in_sizes, int n_in,
                              void* d_out, int out_size) {
    const float* x       = (const float*)d_in[0];
    const float* adj     = (const float*)d_in[1];
    const float* nmask   = (const float*)d_in[2];
    const float* W_embed = (const float*)d_in[3];
    const float* W0      = (const float*)d_in[4];
    const float* b0      = (const float*)d_in[5];
    const float* W1      = (const float*)d_in[6];
    const float* b1      = (const float*)d_in[7];
    const float* W_out   = (const float*)d_in[8];
    const float* b_out   = (const float*)d_in[9];
    float* out = (float*)d_out;

    __half* bufA = nullptr;
    uint16_t* wpre = nullptr;
    cudaGetSymbolAddress((void**)&bufA, g_bufA);
    cudaGetSymbolAddress((void**)&wpre, g_WpreH);

    cudaFuncSetAttribute(kRowH, cudaFuncAttributeMaxDynamicSharedMemorySize, KR_BYTES);
    cudaFuncSetAttribute(kFuse, cudaFuncAttributeMaxDynamicSharedMemorySize, FZ_BYTES);

    kPrep<<<48, 256>>>(W_embed, W0, W1, W_out, wpre);
    kRowH<<<1024, 256, KR_BYTES>>>(x, wpre, b0, bufA);
    kFuse<<<512, 256, FZ_BYTES>>>(adj, bufA, wpre + 4096, wpre + 8192,
                                  b1, b_out, nmask, out);
}

// round 14
// speedup vs baseline: 1.0265x; 1.0265x over previous
#include <cuda_runtime.h>
#include <cuda_fp16.h>
#include <cstdint>

// HGCN (math-reduced), fp16 mma.sync, R10 split pipeline + 512-thread kAdj:
//   kPrep : W01h=half(We@W0z); W1zh/Wozh=half(row0-zeroed W1/W_out)  [k][n]
//   kRowH : S0 = half(x @ W01 + b0)                  (row-major half)
//   kAdjC : S1 = half(relu(adj@S0/100) @ W1z + b1); also writes adj_h=half(adj)
//   kAdjF : out = (relu(adj_h@S1/100) @ Woz + b_out) * mask   (fp32)
// m16n8k16 HMMA fp32-accum; A via ldmatrix.x4 (64B swizzled rows), B/W/T via
// ldmatrix.x4.trans (144B pitch). kAdj kernels: 16 warps, warp tile m32n32,
// 2 CTAs/SM (32 warps/SM), cp.async double-buffered.

static constexpr int NP = 256, HD = 64;

__device__ __half   g_bufA[131072 * 64];     // S0
__device__ __half   g_bufB[131072 * 64];     // S1
__device__ __half   g_adjh[512 * 256 * 256]; // half adj (written by kAdjC)
__device__ uint16_t g_WpreH[3 * 4096];

// ---- kAdjC smem (bytes) ----------------------------------------------------
static constexpr int C_ST = 0;        // fp32 adj stage 256x128B = 32768
static constexpr int C_A0 = 32768;    // half A tile 256x64B (swizzled)
static constexpr int C_A1 = 49152;
static constexpr int C_B0 = 65536;    // S chunk 32x144B = 4608
static constexpr int C_B1 = 70144;
static constexpr int C_W  = 74752;    // 64x144B = 9216
static constexpr int C_BYTES = 83968; // T tile (36864B) overlays offset 0
// ---- kAdjF smem ------------------------------------------------------------
static constexpr int F_A0 = 0;
static constexpr int F_A1 = 16384;
static constexpr int F_B0 = 32768;
static constexpr int F_B1 = 37376;
static constexpr int F_W  = 41984;
static constexpr int F_BYTES = 51200;  // T tile (36864) overlays F_A0..F_B0
// ---- kRowH smem ------------------------------------------------------------
static constexpr int KR_ST   = 0;
static constexpr int KR_XH   = 32768;
static constexpr int KR_W    = 51200;
static constexpr int KR_BIAS = 60416;
static constexpr int KR_BYTES= 60672;

// ---- helpers ---------------------------------------------------------------
__device__ __forceinline__ uint32_t smem_u32(const void* p) {
    uint32_t a;
    asm("{ .reg .u64 t; cvta.to.shared.u64 t, %1; cvt.u32.u64 %0, t; }"
        : "=r"(a) : "l"(p));
    return a;
}
__device__ __forceinline__ void cpa16(uint32_t dst, const void* src) {
    asm volatile("cp.async.ca.shared.global [%0], [%1], 16;\n"
                 :: "r"(dst), "l"(src));
}
__device__ __forceinline__ void ldsm4(uint32_t* r, uint32_t addr) {
    asm volatile("ldmatrix.sync.aligned.m8n8.x4.shared.b16 {%0,%1,%2,%3}, [%4];"
                 : "=r"(r[0]), "=r"(r[1]), "=r"(r[2]), "=r"(r[3]) : "r"(addr));
}
__device__ __forceinline__ void ldsm4t(uint32_t* r, uint32_t addr) {
    asm volatile("ldmatrix.sync.aligned.m8n8.x4.trans.shared.b16 {%0,%1,%2,%3}, [%4];"
                 : "=r"(r[0]), "=r"(r[1]), "=r"(r[2]), "=r"(r[3]) : "r"(addr));
}
__device__ __forceinline__ void mma16(float* c, const uint32_t* a,
                                      uint32_t b0, uint32_t b1) {
    asm volatile(
        "mma.sync.aligned.m16n8k16.row.col.f32.f16.f16.f32 "
        "{%0,%1,%2,%3}, {%4,%5,%6,%7}, {%8,%9}, {%0,%1,%2,%3};\n"
        : "+f"(c[0]), "+f"(c[1]), "+f"(c[2]), "+f"(c[3])
        : "r"(a[0]), "r"(a[1]), "r"(a[2]), "r"(a[3]), "r"(b0), "r"(b1));
}
__device__ __forceinline__ uint32_t pk2h(float a, float b) {
    __half2 h = __floats2half2_rn(a, b);
    return *reinterpret_cast<uint32_t*>(&h);
}
// A-tile swizzle: 64B rows, 16B units; unit' = q ^ ((r>>1)&3)
__device__ __forceinline__ int aswz(int r, int q) {
    return r * 64 + ((q ^ ((r >> 1) & 3)) << 4);
}

// ---------------------------------------------------------------------------
// kPrep: blocks 0..127: W01 = half(We@W0z), 8-way K-split + shfl reduce.
//        blocks 128..159: W1z / Woz row0-zeroed converts.
// ---------------------------------------------------------------------------
__global__ void __launch_bounds__(256)
kPrep(const float* __restrict__ We, const float* __restrict__ W0,
      const float* __restrict__ W1, const float* __restrict__ Wo,
      uint16_t* __restrict__ WpreH) {
    const int blk = blockIdx.x, tid = threadIdx.x;
    if (blk < 128) {
        int out = blk * 32 + (tid >> 3);          // 0..4095
        int r = out >> 6, c = out & 63;
        int l8 = tid & 7;
        float s = 0.f;
        #pragma unroll
        for (int m = 0; m < 8; m++) {
            int k = l8 * 8 + m;
            if (k != 0) s += We[r * 64 + k] * W0[k * 64 + c];
        }
        s += __shfl_down_sync(0xffffffffu, s, 4, 8);
        s += __shfl_down_sync(0xffffffffu, s, 2, 8);
        s += __shfl_down_sync(0xffffffffu, s, 1, 8);
        if (l8 == 0) {
            __half h = __float2half_rn(s);
            WpreH[out] = *reinterpret_cast<uint16_t*>(&h);
        }
    } else {
        int id = (blk - 128) * 256 + tid;         // 0..8191
        int which = 1 + (id >> 12);
        int li = id & 4095;
        int k = li >> 6;
        const float* W = (which == 1) ? W1 : Wo;
        float v = (k == 0) ? 0.f : W[li];
        __half h = __float2half_rn(v);
        WpreH[which * 4096 + li] = *reinterpret_cast<uint16_t*>(&h);
    }
}

// ---------------------------------------------------------------------------
// kRowH (unchanged, passing since R9): S0 = half(x @ W01 + b0)
// ---------------------------------------------------------------------------
__global__ void __launch_bounds__(256, 2)
kRowH(const float* __restrict__ X, const uint16_t* __restrict__ Wh,
      const float* __restrict__ bias, __half* __restrict__ S) {
    extern __shared__ char sm[];
    const uint32_t sb = smem_u32(sm);
    const int tid = threadIdx.x;
    const int lane = tid & 31, w = tid >> 5;
    const int g = lane >> 2;
    const int wm = w & 3, wn = w >> 2;
    const long row0 = (long)blockIdx.x * 128;

    #pragma unroll
    for (int i = 0; i < 8; i++) {
        int u = tid + i * 256;
        cpa16(sb + KR_ST + u * 16, X + (row0 + (u >> 4)) * 64 + (u & 15) * 4);
    }
    #pragma unroll
    for (int i = 0; i < 2; i++) {
        int u = tid + i * 256;
        cpa16(sb + KR_W + (u >> 3) * 144 + (u & 7) * 16,
              Wh + (u >> 3) * 64 + (u & 7) * 8);
    }
    asm volatile("cp.async.commit_group;\n");
    if (tid < HD) *reinterpret_cast<float*>(sm + KR_BIAS + tid * 4) = bias[tid];
    asm volatile("cp.async.wait_group 0;\n");
    __syncthreads();

    #pragma unroll
    for (int i = 0; i < 8; i++) {
        int u = tid + i * 256;
        int r = u >> 4, q = u & 15;
        float4 v = *reinterpret_cast<float4*>(sm + KR_ST + u * 16);
        uint2 h;
        h.x = pk2h(v.x, v.y);
        h.y = pk2h(v.z, v.w);
        *reinterpret_cast<uint2*>(sm + KR_XH + r * 144 + q * 8) = h;
    }
    __syncthreads();

    float acc[2][4][4];
    #pragma unroll
    for (int i = 0; i < 2; i++)
        #pragma unroll
        for (int j = 0; j < 4; j++)
            #pragma unroll
            for (int r = 0; r < 4; r++) acc[i][j][r] = 0.f;

    #pragma unroll
    for (int ks = 0; ks < 4; ks++) {
        uint32_t a[2][4], bb[2][4];
        #pragma unroll
        for (int i = 0; i < 2; i++)
            ldsm4(a[i], sb + KR_XH + (wm * 32 + i * 16 + (lane & 15)) * 144
                        + ks * 32 + (lane >> 4) * 16);
        #pragma unroll
        for (int p = 0; p < 2; p++)
            ldsm4t(bb[p], sb + KR_W + (ks * 16 + (lane & 15)) * 144
                          + (wn * 32 + p * 16 + (lane >> 4) * 8) * 2);
        #pragma unroll
        for (int j = 0; j < 4; j++) {
            uint32_t b0 = bb[j >> 1][(j & 1) * 2];
            uint32_t b1 = bb[j >> 1][(j & 1) * 2 + 1];
            mma16(acc[0][j], a[0], b0, b1);
            mma16(acc[1][j], a[1], b0, b1);
        }
    }

    const float* bsm = reinterpret_cast<const float*>(sm + KR_BIAS);
    #pragma unroll
    for (int i = 0; i < 2; i++)
        #pragma unroll
        for (int j = 0; j < 4; j++) {
            int col = wn * 32 + j * 8 + 2 * (lane & 3);
            float b0 = bsm[col], b1 = bsm[col + 1];
            int r0 = wm * 32 + i * 16 + g;
            uint32_t h0 = pk2h(acc[i][j][0] + b0, acc[i][j][1] + b1);
            uint32_t h1 = pk2h(acc[i][j][2] + b0, acc[i][j][3] + b1);
            *reinterpret_cast<uint32_t*>(S + (row0 + r0) * 64 + col)     = h0;
            *reinterpret_cast<uint32_t*>(S + (row0 + r0 + 8) * 64 + col) = h1;
        }
}

// ---------------------------------------------------------------------------
// kAdjC: 512 threads, warp tile m32n32. fp32 adj in; writes S1 + adj_h.
// ---------------------------------------------------------------------------
__global__ void __launch_bounds__(512, 2)
kAdjC(const float* __restrict__ adj, const __half* __restrict__ S,
      const uint16_t* __restrict__ Wh, const float* __restrict__ bias,
      __half* __restrict__ S1, __half* __restrict__ adjh) {
    extern __shared__ char sm[];
    const uint32_t sb = smem_u32(sm);
    const int tid = threadIdx.x;
    const int lane = tid & 31, w = tid >> 5;
    const int g = lane >> 2, t = lane & 3;
    const int wm = w & 7, wn = w >> 3;        // 8m x 2n warps, tile m32n32
    const int b = blockIdx.x;

    const float*  adjb  = adj + (size_t)b * NP * NP;
    const __half* Sb    = S + (size_t)b * NP * HD;
    __half*       adjhb = adjh + (size_t)b * NP * NP;

    auto prefetch = [&](int c) {
        #pragma unroll
        for (int i = 0; i < 4; i++) {         // fp32 stage: 2048 units
            int u = tid + i * 512;
            cpa16(sb + C_ST + u * 16, adjb + (size_t)(u >> 3) * NP + c * 32 + (u & 7) * 4);
        }
        if (tid < 256) {                      // S chunk: 256 units
            int r = tid >> 3, q = tid & 7;
            cpa16(sb + ((c & 1) ? C_B1 : C_B0) + r * 144 + q * 16,
                  Sb + (size_t)(c * 32 + r) * HD + q * 8);
        }
        asm volatile("cp.async.commit_group;\n");
    };

    // prologue: W tile + chunk 0
    {
        int r = tid >> 3, q = tid & 7;        // 512 units
        cpa16(sb + C_W + r * 144 + q * 16, Wh + r * 64 + q * 8);
    }
    prefetch(0);

    float acc[2][4][4];
    #pragma unroll
    for (int i = 0; i < 2; i++)
        #pragma unroll
        for (int j = 0; j < 4; j++)
            #pragma unroll
            for (int r = 0; r < 4; r++) acc[i][j][r] = 0.f;

    for (int c = 0; c < 8; c++) {
        asm volatile("cp.async.wait_group 0;\n");
        __syncthreads();                      // stage(c)+B(c&1) in; mma(c-1) done

        const int AH = (c & 1) ? C_A1 : C_A0;
        #pragma unroll
        for (int i = 0; i < 4; i++) {
            int u = tid + i * 512;
            int r = u >> 3, q32 = u & 7;
            float4 v = *reinterpret_cast<float4*>(sm + C_ST + u * 16);
            uint2 h;
            h.x = pk2h(v.x, v.y);
            h.y = pk2h(v.z, v.w);
            *reinterpret_cast<uint2*>(sm + AH + aswz(r, q32 >> 1) + (q32 & 1) * 8) = h;
            *reinterpret_cast<uint2*>(adjhb + (size_t)r * NP + c * 32 + q32 * 4) = h;
        }
        __syncthreads();                      // AH visible; stage consumed

        if (c + 1 < 8) prefetch(c + 1);       // overlaps mma below

        const int BH = (c & 1) ? C_B1 : C_B0;
        #pragma unroll
        for (int s = 0; s < 2; s++) {
            uint32_t a[2][4], bb[2][4];
            #pragma unroll
            for (int i = 0; i < 2; i++) {
                int r = wm * 32 + i * 16 + (lane & 15);
                ldsm4(a[i], sb + AH + aswz(r, 2 * s + (lane >> 4)));
            }
            #pragma unroll
            for (int p = 0; p < 2; p++)
                ldsm4t(bb[p], sb + BH + (s * 16 + (lane & 15)) * 144
                              + (wn * 32 + p * 16 + (lane >> 4) * 8) * 2);
            #pragma unroll
            for (int j = 0; j < 4; j++) {
                uint32_t b0 = bb[j >> 1][(j & 1) * 2];
                uint32_t b1 = bb[j >> 1][(j & 1) * 2 + 1];
                #pragma unroll
                for (int i = 0; i < 2; i++) mma16(acc[i][j], a[i], b0, b1);
            }
        }
    }

    __syncthreads();                          // tiles dead -> T overlay @ 0

    #pragma unroll
    for (int i = 0; i < 2; i++)
        #pragma unroll
        for (int j = 0; j < 4; j++) {
            int r0 = wm * 32 + i * 16 + g;
            int col = wn * 32 + j * 8 + 2 * t;
            uint32_t h0 = pk2h(fmaxf(acc[i][j][0] * 0.01f, 0.f),
                               fmaxf(acc[i][j][1] * 0.01f, 0.f));
            uint32_t h1 = pk2h(fmaxf(acc[i][j][2] * 0.01f, 0.f),
                               fmaxf(acc[i][j][3] * 0.01f, 0.f));
            *reinterpret_cast<uint32_t*>(sm + r0 * 144 + col * 2)       = h0;
            *reinterpret_cast<uint32_t*>(sm + (r0 + 8) * 144 + col * 2) = h1;
        }
    __syncthreads();

    #pragma unroll
    for (int i = 0; i < 2; i++)
        #pragma unroll
        for (int j = 0; j < 4; j++)
            #pragma unroll
            for (int r = 0; r < 4; r++) acc[i][j][r] = 0.f;

    #pragma unroll
    for (int ks = 0; ks < 4; ks++) {
        uint32_t a[2][4], bb[2][4];
        #pragma unroll
        for (int i = 0; i < 2; i++)
            ldsm4(a[i], sb + (wm * 32 + i * 16 + (lane & 15)) * 144
                        + ks * 32 + (lane >> 4) * 16);
        #pragma unroll
        for (int p = 0; p < 2; p++)
            ldsm4t(bb[p], sb + C_W + (ks * 16 + (lane & 15)) * 144
                          + (wn * 32 + p * 16 + (lane >> 4) * 8) * 2);
        #pragma unroll
        for (int j = 0; j < 4; j++) {
            uint32_t b0 = bb[j >> 1][(j & 1) * 2];
            uint32_t b1 = bb[j >> 1][(j & 1) * 2 + 1];
            #pragma unroll
            for (int i = 0; i < 2; i++) mma16(acc[i][j], a[i], b0, b1);
        }
    }

    #pragma unroll
    for (int j = 0; j < 4; j++) {
        int col = wn * 32 + j * 8 + 2 * t;
        float b0 = bias[col], b1 = bias[col + 1];
        #pragma unroll
        for (int i = 0; i < 2; i++) {
            int r0 = wm * 32 + i * 16 + g;
            uint32_t h0 = pk2h(acc[i][j][0] + b0, acc[i][j][1] + b1);
            uint32_t h1 = pk2h(acc[i][j][2] + b0, acc[i][j][3] + b1);
            *reinterpret_cast<uint32_t*>(S1 + ((size_t)b * NP + r0) * HD + col)     = h0;
            *reinterpret_cast<uint32_t*>(S1 + ((size_t)b * NP + r0 + 8) * HD + col) = h1;
        }
    }
}

// ---------------------------------------------------------------------------
// kAdjF: 512 threads, warp tile m32n32. half adj in; fp32 masked out.
// ---------------------------------------------------------------------------
__global__ void __launch_bounds__(512, 2)
kAdjF(const __half* __restrict__ adjh, const __half* __restrict__ S,
      const uint16_t* __restrict__ Wh, const float* __restrict__ bias,
      const float* __restrict__ nmask, float* __restrict__ out) {
    extern __shared__ char sm[];
    const uint32_t sb = smem_u32(sm);
    const int tid = threadIdx.x;
    const int lane = tid & 31, w = tid >> 5;
    const int g = lane >> 2, t = lane & 3;
    const int wm = w & 7, wn = w >> 3;
    const int b = blockIdx.x;

    const __half* adjb = adjh + (size_t)b * NP * NP;
    const __half* Sb   = S + (size_t)b * NP * HD;

    auto prefetch = [&](int c) {
        const int AH = (c & 1) ? F_A1 : F_A0;
        #pragma unroll
        for (int i = 0; i < 2; i++) {         // A: 1024 units (swizzled in)
            int u = tid + i * 512;
            int r = u >> 2, q = u & 3;
            cpa16(sb + AH + aswz(r, q), adjb + (size_t)r * NP + c * 32 + q * 8);
        }
        if (tid < 256) {                      // B: 256 units
            int r = tid >> 3, q = tid & 7;
            cpa16(sb + ((c & 1) ? F_B1 : F_B0) + r * 144 + q * 16,
                  Sb + (size_t)(c * 32 + r) * HD + q * 8);
        }
        asm volatile("cp.async.commit_group;\n");
    };

    // prologue: W tile + chunk 0 (one group)
    {
        int r = tid >> 3, q = tid & 7;
        cpa16(sb + F_W + r * 144 + q * 16, Wh + r * 64 + q * 8);
    }
    prefetch(0);

    float acc[2][4][4];
    #pragma unroll
    for (int i = 0; i < 2; i++)
        #pragma unroll
        for (int j = 0; j < 4; j++)
            #pragma unroll
            for (int r = 0; r < 4; r++) acc[i][j][r] = 0.f;

    for (int c = 0; c < 8; c++) {
        asm volatile("cp.async.wait_group 0;\n");
        __syncthreads();                      // chunk c in; mma(c-1) done
        if (c + 1 < 8) prefetch(c + 1);       // overlaps mma(c)

        const int AH = (c & 1) ? F_A1 : F_A0;
        const int BH = (c & 1) ? F_B1 : F_B0;
        #pragma unroll
        for (int s = 0; s < 2; s++) {
            uint32_t a[2][4], bb[2][4];
            #pragma unroll
            for (int i = 0; i < 2; i++) {
                int r = wm * 32 + i * 16 + (lane & 15);
                ldsm4(a[i], sb + AH + aswz(r, 2 * s + (lane >> 4)));
            }
            #pragma unroll
            for (int p = 0; p < 2; p++)
                ldsm4t(bb[p], sb + BH + (s * 16 + (lane & 15)) * 144
                              + (wn * 32 + p * 16 + (lane >> 4) * 8) * 2);
            #pragma unroll
            for (int j = 0; j < 4; j++) {
                uint32_t b0 = bb[j >> 1][(j & 1) * 2];
                uint32_t b1 = bb[j >> 1][(j & 1) * 2 + 1];
                #pragma unroll
                for (int i = 0; i < 2; i++) mma16(acc[i][j], a[i], b0, b1);
            }
        }
    }

    __syncthreads();                          // tiles dead -> T overlay @ 0

    #pragma unroll
    for (int i = 0; i < 2; i++)
        #pragma unroll
        for (int j = 0; j < 4; j++) {
            int r0 = wm * 32 + i * 16 + g;
            int col = wn * 32 + j * 8 + 2 * t;
            uint32_t h0 = pk2h(fmaxf(acc[i][j][0] * 0.01f, 0.f),
                               fmaxf(acc[i][j][1] * 0.01f, 0.f));
            uint32_t h1 = pk2h(fmaxf(acc[i][j][2] * 0.01f, 0.f),
                               fmaxf(acc[i][j][3] * 0.01f, 0.f));
            *reinterpret_cast<uint32_t*>(sm + r0 * 144 + col * 2)       = h0;
            *reinterpret_cast<uint32_t*>(sm + (r0 + 8) * 144 + col * 2) = h1;
        }
    __syncthreads();

    #pragma unroll
    for (int i = 0; i < 2; i++)
        #pragma unroll
        for (int j = 0; j < 4; j++)
            #pragma unroll
            for (int r = 0; r < 4; r++) acc[i][j][r] = 0.f;

    #pragma unroll
    for (int ks = 0; ks < 4; ks++) {
        uint32_t a[2][4], bb[2][4];
        #pragma unroll
        for (int i = 0; i < 2; i++)
            ldsm4(a[i], sb + (wm * 32 + i * 16 + (lane & 15)) * 144
                        + ks * 32 + (lane >> 4) * 16);
        #pragma unroll
        for (int p = 0; p < 2; p++)
            ldsm4t(bb[p], sb + F_W + (ks * 16 + (lane & 15)) * 144
                          + (wn * 32 + p * 16 + (lane >> 4) * 8) * 2);
        #pragma unroll
        for (int j = 0; j < 4; j++) {
            uint32_t b0 = bb[j >> 1][(j & 1) * 2];
            uint32_t b1 = bb[j >> 1][(j & 1) * 2 + 1];
            #pragma unroll
            for (int i = 0; i < 2; i++) mma16(acc[i][j], a[i], b0, b1);
        }
    }

    const float* mrow = nmask + (size_t)b * NP;
    #pragma unroll
    for (int j = 0; j < 4; j++) {
        int col = wn * 32 + j * 8 + 2 * t;
        float b0 = bias[col], b1 = bias[col + 1];
        #pragma unroll
        for (int i = 0; i < 2; i++) {
            int r0 = wm * 32 + i * 16 + g;
            float m0 = mrow[r0], m1 = mrow[r0 + 8];
            float2 v0, v1;
            v0.x = (acc[i][j][0] + b0) * m0;
            v0.y = (acc[i][j][1] + b1) * m0;
            v1.x = (acc[i][j][2] + b0) * m1;
            v1.y = (acc[i][j][3] + b1) * m1;
            *reinterpret_cast<float2*>(out + ((size_t)b * NP + r0) * HD + col)     = v0;
            *reinterpret_cast<float2*>(out + ((size_t)b * NP + r0 + 8) * HD + col) = v1;
        }
    }
}

// ---------------------------------------------------------------------------
extern "C" void kernel_launch(void* const* d_in, const int* in_sizes, int n_in,
                              void* d_out, int out_size) {
    const float* x       = (const float*)d_in[0];
    const float* adj     = (const float*)d_in[1];
    const float* nmask   = (const float*)d_in[2];
    const float* W_embed = (const float*)d_in[3];
    const float* W0      = (const float*)d_in[4];
    const float* b0      = (const float*)d_in[5];
    const float* W1      = (const float*)d_in[6];
    const float* b1      = (const float*)d_in[7];
    const float* W_out   = (const float*)d_in[8];
    const float* b_out   = (const float*)d_in[9];
    float* out = (float*)d_out;

    __half *bufA = nullptr, *bufB = nullptr, *adjh = nullptr;
    uint16_t* wpre = nullptr;
    cudaGetSymbolAddress((void**)&bufA, g_bufA);
    cudaGetSymbolAddress((void**)&bufB, g_bufB);
    cudaGetSymbolAddress((void**)&adjh, g_adjh);
    cudaGetSymbolAddress((void**)&wpre, g_WpreH);

    cudaFuncSetAttribute(kRowH, cudaFuncAttributeMaxDynamicSharedMemorySize, KR_BYTES);
    cudaFuncSetAttribute(kAdjC, cudaFuncAttributeMaxDynamicSharedMemorySize, C_BYTES);
    cudaFuncSetAttribute(kAdjF, cudaFuncAttributeMaxDynamicSharedMemorySize, F_BYTES);

    kPrep<<<160, 256>>>(W_embed, W0, W1, W_out, wpre);
    kRowH<<<1024, 256, KR_BYTES>>>(x, wpre, b0, bufA);
    kAdjC<<<512, 512, C_BYTES>>>(adj, bufA, wpre + 4096, b1, bufB, adjh);
    kAdjF<<<512, 512, F_BYTES>>>(adjh, bufB, wpre + 8192, b_out, nmask, out);
}

// round 15
// speedup vs baseline: 1.1000x; 1.0716x over previous
#include <cuda_runtime.h>
#include <cuda_fp16.h>
#include <cstdint>

// HGCN (math-reduced), fp16 mma.sync — R10 pipeline (best: 105.4us) with the
// R14 parallel kPrep (R10's serial kPrep measured 7.8us, 7% of runtime):
//   kPrep : W01h=half(We@W0z); W1zh/Wozh=half(row0-zeroed W1/W_out)  [k][n]
//   kRowH : S0 = half(x @ W01 + b0)                  (row-major half)
//   kAdjC : S1 = half(relu(adj@S0/100) @ W1z + b1); also writes adj_h=half(adj)
//   kAdjF : out = (relu(adj_h@S1/100) @ Woz + b_out) * mask   (fp32)
// m16n8k16 HMMA fp32-accum; A via ldmatrix.x4 (64B swizzled rows), B/W/T via
// ldmatrix.x4.trans (144B pitch). kAdj: 256 threads, warp tile m64n32.

static constexpr int NP = 256, HD = 64;

__device__ __half   g_bufA[131072 * 64];     // S0
__device__ __half   g_bufB[131072 * 64];     // S1
__device__ __half   g_adjh[512 * 256 * 256]; // half adj (written by kAdjC)
__device__ uint16_t g_WpreH[3 * 4096];

// ---- kAdjC smem (bytes) ----------------------------------------------------
static constexpr int C_ST = 0;        // fp32 adj stage 256x128B = 32768
static constexpr int C_A0 = 32768;    // half A tile 256x64B (swizzled)
static constexpr int C_A1 = 49152;
static constexpr int C_B0 = 65536;    // S chunk 32x144B = 4608
static constexpr int C_B1 = 70144;
static constexpr int C_W  = 74752;    // 64x144B = 9216
static constexpr int C_BYTES = 83968; // T tile (36864B) overlays offset 0
// ---- kAdjF smem ------------------------------------------------------------
static constexpr int F_A0 = 0;
static constexpr int F_A1 = 16384;
static constexpr int F_B0 = 32768;
static constexpr int F_B1 = 37376;
static constexpr int F_W  = 41984;
static constexpr int F_BYTES = 51200;
// ---- kRowH smem ------------------------------------------------------------
static constexpr int KR_ST   = 0;
static constexpr int KR_XH   = 32768;
static constexpr int KR_W    = 51200;
static constexpr int KR_BIAS = 60416;
static constexpr int KR_BYTES= 60672;

// ---- helpers ---------------------------------------------------------------
__device__ __forceinline__ uint32_t smem_u32(const void* p) {
    uint32_t a;
    asm("{ .reg .u64 t; cvta.to.shared.u64 t, %1; cvt.u32.u64 %0, t; }"
        : "=r"(a) : "l"(p));
    return a;
}
__device__ __forceinline__ void cpa16(uint32_t dst, const void* src) {
    asm volatile("cp.async.ca.shared.global [%0], [%1], 16;\n"
                 :: "r"(dst), "l"(src));
}
__device__ __forceinline__ void ldsm4(uint32_t* r, uint32_t addr) {
    asm volatile("ldmatrix.sync.aligned.m8n8.x4.shared.b16 {%0,%1,%2,%3}, [%4];"
                 : "=r"(r[0]), "=r"(r[1]), "=r"(r[2]), "=r"(r[3]) : "r"(addr));
}
__device__ __forceinline__ void ldsm4t(uint32_t* r, uint32_t addr) {
    asm volatile("ldmatrix.sync.aligned.m8n8.x4.trans.shared.b16 {%0,%1,%2,%3}, [%4];"
                 : "=r"(r[0]), "=r"(r[1]), "=r"(r[2]), "=r"(r[3]) : "r"(addr));
}
__device__ __forceinline__ void mma16(float* c, const uint32_t* a,
                                      uint32_t b0, uint32_t b1) {
    asm volatile(
        "mma.sync.aligned.m16n8k16.row.col.f32.f16.f16.f32 "
        "{%0,%1,%2,%3}, {%4,%5,%6,%7}, {%8,%9}, {%0,%1,%2,%3};\n"
        : "+f"(c[0]), "+f"(c[1]), "+f"(c[2]), "+f"(c[3])
        : "r"(a[0]), "r"(a[1]), "r"(a[2]), "r"(a[3]), "r"(b0), "r"(b1));
}
__device__ __forceinline__ uint32_t pk2h(float a, float b) {
    __half2 h = __floats2half2_rn(a, b);
    return *reinterpret_cast<uint32_t*>(&h);
}
// A-tile swizzle: 64B rows, 16B units; unit' = q ^ ((r>>1)&3)
__device__ __forceinline__ int aswz(int r, int q) {
    return r * 64 + ((q ^ ((r >> 1) & 3)) << 4);
}

// ---------------------------------------------------------------------------
// kPrep (parallel, R14): blocks 0..127: W01 = half(We@W0z), 8-way K-split +
// shfl reduce. blocks 128..159: W1z / Woz row0-zeroed converts.
// ---------------------------------------------------------------------------
__global__ void __launch_bounds__(256)
kPrep(const float* __restrict__ We, const float* __restrict__ W0,
      const float* __restrict__ W1, const float* __restrict__ Wo,
      uint16_t* __restrict__ WpreH) {
    const int blk = blockIdx.x, tid = threadIdx.x;
    if (blk < 128) {
        int out = blk * 32 + (tid >> 3);          // 0..4095
        int r = out >> 6, c = out & 63;
        int l8 = tid & 7;
        float s = 0.f;
        #pragma unroll
        for (int m = 0; m < 8; m++) {
            int k = l8 * 8 + m;
            if (k != 0) s += We[r * 64 + k] * W0[k * 64 + c];
        }
        s += __shfl_down_sync(0xffffffffu, s, 4, 8);
        s += __shfl_down_sync(0xffffffffu, s, 2, 8);
        s += __shfl_down_sync(0xffffffffu, s, 1, 8);
        if (l8 == 0) {
            __half h = __float2half_rn(s);
            WpreH[out] = *reinterpret_cast<uint16_t*>(&h);
        }
    } else {
        int id = (blk - 128) * 256 + tid;         // 0..8191
        int which = 1 + (id >> 12);
        int li = id & 4095;
        int k = li >> 6;
        const float* W = (which == 1) ? W1 : Wo;
        float v = (k == 0) ? 0.f : W[li];
        __half h = __float2half_rn(v);
        WpreH[which * 4096 + li] = *reinterpret_cast<uint16_t*>(&h);
    }
}

// ---------------------------------------------------------------------------
// kRowH (R10 verbatim): S0 = half(x @ W01 + b0)
// ---------------------------------------------------------------------------
__global__ void __launch_bounds__(256, 2)
kRowH(const float* __restrict__ X, const uint16_t* __restrict__ Wh,
      const float* __restrict__ bias, __half* __restrict__ S) {
    extern __shared__ char sm[];
    const uint32_t sb = smem_u32(sm);
    const int tid = threadIdx.x;
    const int lane = tid & 31, w = tid >> 5;
    const int g = lane >> 2;
    const int wm = w & 3, wn = w >> 2;
    const long row0 = (long)blockIdx.x * 128;

    #pragma unroll
    for (int i = 0; i < 8; i++) {
        int u = tid + i * 256;
        cpa16(sb + KR_ST + u * 16, X + (row0 + (u >> 4)) * 64 + (u & 15) * 4);
    }
    #pragma unroll
    for (int i = 0; i < 2; i++) {
        int u = tid + i * 256;
        cpa16(sb + KR_W + (u >> 3) * 144 + (u & 7) * 16,
              Wh + (u >> 3) * 64 + (u & 7) * 8);
    }
    asm volatile("cp.async.commit_group;\n");
    if (tid < HD) *reinterpret_cast<float*>(sm + KR_BIAS + tid * 4) = bias[tid];
    asm volatile("cp.async.wait_group 0;\n");
    __syncthreads();

    #pragma unroll
    for (int i = 0; i < 8; i++) {
        int u = tid + i * 256;
        int r = u >> 4, q = u & 15;
        float4 v = *reinterpret_cast<float4*>(sm + KR_ST + u * 16);
        uint2 h;
        h.x = pk2h(v.x, v.y);
        h.y = pk2h(v.z, v.w);
        *reinterpret_cast<uint2*>(sm + KR_XH + r * 144 + q * 8) = h;
    }
    __syncthreads();

    float acc[2][4][4];
    #pragma unroll
    for (int i = 0; i < 2; i++)
        #pragma unroll
        for (int j = 0; j < 4; j++)
            #pragma unroll
            for (int r = 0; r < 4; r++) acc[i][j][r] = 0.f;

    #pragma unroll
    for (int ks = 0; ks < 4; ks++) {
        uint32_t a[2][4], bb[2][4];
        #pragma unroll
        for (int i = 0; i < 2; i++)
            ldsm4(a[i], sb + KR_XH + (wm * 32 + i * 16 + (lane & 15)) * 144
                        + ks * 32 + (lane >> 4) * 16);
        #pragma unroll
        for (int p = 0; p < 2; p++)
            ldsm4t(bb[p], sb + KR_W + (ks * 16 + (lane & 15)) * 144
                          + (wn * 32 + p * 16 + (lane >> 4) * 8) * 2);
        #pragma unroll
        for (int j = 0; j < 4; j++) {
            uint32_t b0 = bb[j >> 1][(j & 1) * 2];
            uint32_t b1 = bb[j >> 1][(j & 1) * 2 + 1];
            mma16(acc[0][j], a[0], b0, b1);
            mma16(acc[1][j], a[1], b0, b1);
        }
    }

    const float* bsm = reinterpret_cast<const float*>(sm + KR_BIAS);
    #pragma unroll
    for (int i = 0; i < 2; i++)
        #pragma unroll
        for (int j = 0; j < 4; j++) {
            int col = wn * 32 + j * 8 + 2 * (lane & 3);
            float b0 = bsm[col], b1 = bsm[col + 1];
            int r0 = wm * 32 + i * 16 + g;
            uint32_t h0 = pk2h(acc[i][j][0] + b0, acc[i][j][1] + b1);
            uint32_t h1 = pk2h(acc[i][j][2] + b0, acc[i][j][3] + b1);
            *reinterpret_cast<uint32_t*>(S + (row0 + r0) * 64 + col)     = h0;
            *reinterpret_cast<uint32_t*>(S + (row0 + r0 + 8) * 64 + col) = h1;
        }
}

// ---------------------------------------------------------------------------
// kAdjC (R10 verbatim): fp32 adj in; writes S1 (half) and adj_h (half).
// ---------------------------------------------------------------------------
__global__ void __launch_bounds__(256, 2)
kAdjC(const float* __restrict__ adj, const __half* __restrict__ S,
      const uint16_t* __restrict__ Wh, const float* __restrict__ bias,
      __half* __restrict__ S1, __half* __restrict__ adjh) {
    extern __shared__ char sm[];
    const uint32_t sb = smem_u32(sm);
    const int tid = threadIdx.x;
    const int lane = tid & 31, w = tid >> 5;
    const int g = lane >> 2, t = lane & 3;
    const int wm = w & 3, wn = w >> 2;
    const int b = blockIdx.x;

    const float*  adjb  = adj + (size_t)b * NP * NP;
    const __half* Sb    = S + (size_t)b * NP * HD;
    __half*       adjhb = adjh + (size_t)b * NP * NP;

    #pragma unroll
    for (int i = 0; i < 8; i++) {
        int u = tid + i * 256;
        cpa16(sb + C_ST + u * 16, adjb + (size_t)(u >> 3) * NP + (u & 7) * 4);
    }
    #pragma unroll
    for (int i = 0; i < 2; i++) {
        int u = tid + i * 256;
        cpa16(sb + C_W + (u >> 3) * 144 + (u & 7) * 16,
              Wh + (u >> 3) * 64 + (u & 7) * 8);
    }
    asm volatile("cp.async.commit_group;\n");
    uint4 rB = *reinterpret_cast<const uint4*>(Sb + (size_t)(tid >> 3) * HD + (tid & 7) * 8);

    float acc[4][4][4];
    #pragma unroll
    for (int i = 0; i < 4; i++)
        #pragma unroll
        for (int j = 0; j < 4; j++)
            #pragma unroll
            for (int r = 0; r < 4; r++) acc[i][j][r] = 0.f;

    for (int c = 0; c < 8; c++) {
        asm volatile("cp.async.wait_group 0;\n");
        __syncthreads();                          // stage(c) visible everywhere

        const int AH = (c & 1) ? C_A1 : C_A0;
        const int BH = (c & 1) ? C_B1 : C_B0;
        #pragma unroll
        for (int i = 0; i < 8; i++) {
            int u = tid + i * 256;
            int r = u >> 3, q32 = u & 7;
            float4 v = *reinterpret_cast<float4*>(sm + C_ST + u * 16);
            uint2 h;
            h.x = pk2h(v.x, v.y);
            h.y = pk2h(v.z, v.w);
            *reinterpret_cast<uint2*>(sm + AH + aswz(r, q32 >> 1) + (q32 & 1) * 8) = h;
            *reinterpret_cast<uint2*>(adjhb + (size_t)r * NP + c * 32 + q32 * 4) = h;
        }
        *reinterpret_cast<uint4*>(sm + BH + (tid >> 3) * 144 + (tid & 7) * 16) = rB;
        if (c + 1 < 8)
            rB = *reinterpret_cast<const uint4*>(
                Sb + (size_t)((c + 1) * 32 + (tid >> 3)) * HD + (tid & 7) * 8);
        __syncthreads();                          // halves visible; stage read

        if (c + 1 < 8) {
            #pragma unroll
            for (int i = 0; i < 8; i++) {
                int u = tid + i * 256;
                cpa16(sb + C_ST + u * 16,
                      adjb + (size_t)(u >> 3) * NP + (c + 1) * 32 + (u & 7) * 4);
            }
            asm volatile("cp.async.commit_group;\n");
        }

        #pragma unroll
        for (int s = 0; s < 2; s++) {
            uint32_t a[4][4], bb[2][4];
            #pragma unroll
            for (int i = 0; i < 4; i++) {
                int r = wm * 64 + i * 16 + (lane & 15);
                ldsm4(a[i], sb + AH + aswz(r, 2 * s + (lane >> 4)));
            }
            #pragma unroll
            for (int p = 0; p < 2; p++)
                ldsm4t(bb[p], sb + BH + (s * 16 + (lane & 15)) * 144
                              + (wn * 32 + p * 16 + (lane >> 4) * 8) * 2);
            #pragma unroll
            for (int j = 0; j < 4; j++) {
                uint32_t b0 = bb[j >> 1][(j & 1) * 2];
                uint32_t b1 = bb[j >> 1][(j & 1) * 2 + 1];
                #pragma unroll
                for (int i = 0; i < 4; i++) mma16(acc[i][j], a[i], b0, b1);
            }
        }
    }

    __syncthreads();                              // everything dead -> T overlay

    #pragma unroll
    for (int i = 0; i < 4; i++)
        #pragma unroll
        for (int j = 0; j < 4; j++) {
            int r0 = wm * 64 + i * 16 + g;
            int col = wn * 32 + j * 8 + 2 * t;
            uint32_t h0 = pk2h(fmaxf(acc[i][j][0] * 0.01f, 0.f),
                               fmaxf(acc[i][j][1] * 0.01f, 0.f));
            uint32_t h1 = pk2h(fmaxf(acc[i][j][2] * 0.01f, 0.f),
                               fmaxf(acc[i][j][3] * 0.01f, 0.f));
            *reinterpret_cast<uint32_t*>(sm + r0 * 144 + col * 2)       = h0;
            *reinterpret_cast<uint32_t*>(sm + (r0 + 8) * 144 + col * 2) = h1;
        }
    __syncthreads();

    #pragma unroll
    for (int i = 0; i < 4; i++)
        #pragma unroll
        for (int j = 0; j < 4; j++)
            #pragma unroll
            for (int r = 0; r < 4; r++) acc[i][j][r] = 0.f;

    #pragma unroll
    for (int ks = 0; ks < 4; ks++) {
        uint32_t a[4][4], bb[2][4];
        #pragma unroll
        for (int i = 0; i < 4; i++)
            ldsm4(a[i], sb + (wm * 64 + i * 16 + (lane & 15)) * 144
                        + ks * 32 + (lane >> 4) * 16);
        #pragma unroll
        for (int p = 0; p < 2; p++)
            ldsm4t(bb[p], sb + C_W + (ks * 16 + (lane & 15)) * 144
                          + (wn * 32 + p * 16 + (lane >> 4) * 8) * 2);
        #pragma unroll
        for (int j = 0; j < 4; j++) {
            uint32_t b0 = bb[j >> 1][(j & 1) * 2];
            uint32_t b1 = bb[j >> 1][(j & 1) * 2 + 1];
            #pragma unroll
            for (int i = 0; i < 4; i++) mma16(acc[i][j], a[i], b0, b1);
        }
    }

    #pragma unroll
    for (int j = 0; j < 4; j++) {
        int col = wn * 32 + j * 8 + 2 * t;
        float b0 = bias[col], b1 = bias[col + 1];
        #pragma unroll
        for (int i = 0; i < 4; i++) {
            int r0 = wm * 64 + i * 16 + g;
            uint32_t h0 = pk2h(acc[i][j][0] + b0, acc[i][j][1] + b1);
            uint32_t h1 = pk2h(acc[i][j][2] + b0, acc[i][j][3] + b1);
            *reinterpret_cast<uint32_t*>(S1 + ((size_t)b * NP + r0) * HD + col)     = h0;
            *reinterpret_cast<uint32_t*>(S1 + ((size_t)b * NP + r0 + 8) * HD + col) = h1;
        }
    }
}

// ---------------------------------------------------------------------------
// kAdjF (R10 verbatim): half adj in; out = (relu(adj_h@S1/100)@Woz+b)*mask.
// ---------------------------------------------------------------------------
__global__ void __launch_bounds__(256, 2)
kAdjF(const __half* __restrict__ adjh, const __half* __restrict__ S,
      const uint16_t* __restrict__ Wh, const float* __restrict__ bias,
      const float* __restrict__ nmask, float* __restrict__ out) {
    extern __shared__ char sm[];
    const uint32_t sb = smem_u32(sm);
    const int tid = threadIdx.x;
    const int lane = tid & 31, w = tid >> 5;
    const int g = lane >> 2, t = lane & 3;
    const int wm = w & 3, wn = w >> 2;
    const int b = blockIdx.x;

    const __half* adjb = adjh + (size_t)b * NP * NP;
    const __half* Sb   = S + (size_t)b * NP * HD;

    #pragma unroll
    for (int i = 0; i < 2; i++) {
        int u = tid + i * 256;
        cpa16(sb + F_W + (u >> 3) * 144 + (u & 7) * 16,
              Wh + (u >> 3) * 64 + (u & 7) * 8);
    }
    asm volatile("cp.async.commit_group;\n");

    uint4 rA[4];
    #pragma unroll
    for (int i = 0; i < 4; i++) {
        int u = tid + i * 256;
        rA[i] = *reinterpret_cast<const uint4*>(
            adjb + (size_t)(u >> 2) * NP + (u & 3) * 8);
    }
    uint4 rB = *reinterpret_cast<const uint4*>(Sb + (size_t)(tid >> 3) * HD + (tid & 7) * 8);

    float acc[4][4][4];
    #pragma unroll
    for (int i = 0; i < 4; i++)
        #pragma unroll
        for (int j = 0; j < 4; j++)
            #pragma unroll
            for (int r = 0; r < 4; r++) acc[i][j][r] = 0.f;

    for (int c = 0; c < 8; c++) {
        const int AH = (c & 1) ? F_A1 : F_A0;
        const int BH = (c & 1) ? F_B1 : F_B0;
        #pragma unroll
        for (int i = 0; i < 4; i++) {
            int u = tid + i * 256;
            *reinterpret_cast<uint4*>(sm + AH + aswz(u >> 2, u & 3)) = rA[i];
        }
        *reinterpret_cast<uint4*>(sm + BH + (tid >> 3) * 144 + (tid & 7) * 16) = rB;
        if (c + 1 < 8) {
            #pragma unroll
            for (int i = 0; i < 4; i++) {
                int u = tid + i * 256;
                rA[i] = *reinterpret_cast<const uint4*>(
                    adjb + (size_t)(u >> 2) * NP + (c + 1) * 32 + (u & 3) * 8);
            }
            rB = *reinterpret_cast<const uint4*>(
                Sb + (size_t)((c + 1) * 32 + (tid >> 3)) * HD + (tid & 7) * 8);
        }
        __syncthreads();                          // single barrier per chunk

        #pragma unroll
        for (int s = 0; s < 2; s++) {
            uint32_t a[4][4], bb[2][4];
            #pragma unroll
            for (int i = 0; i < 4; i++) {
                int r = wm * 64 + i * 16 + (lane & 15);
                ldsm4(a[i], sb + AH + aswz(r, 2 * s + (lane >> 4)));
            }
            #pragma unroll
            for (int p = 0; p < 2; p++)
                ldsm4t(bb[p], sb + BH + (s * 16 + (lane & 15)) * 144
                              + (wn * 32 + p * 16 + (lane >> 4) * 8) * 2);
            #pragma unroll
            for (int j = 0; j < 4; j++) {
                uint32_t b0 = bb[j >> 1][(j & 1) * 2];
                uint32_t b1 = bb[j >> 1][(j & 1) * 2 + 1];
                #pragma unroll
                for (int i = 0; i < 4; i++) mma16(acc[i][j], a[i], b0, b1);
            }
        }
    }

    asm volatile("cp.async.wait_group 0;\n");     // W resident
    __syncthreads();                              // tiles dead -> T overlay

    #pragma unroll
    for (int i = 0; i < 4; i++)
        #pragma unroll
        for (int j = 0; j < 4; j++) {
            int r0 = wm * 64 + i * 16 + g;
            int col = wn * 32 + j * 8 + 2 * t;
            uint32_t h0 = pk2h(fmaxf(acc[i][j][0] * 0.01f, 0.f),
                               fmaxf(acc[i][j][1] * 0.01f, 0.f));
            uint32_t h1 = pk2h(fmaxf(acc[i][j][2] * 0.01f, 0.f),
                               fmaxf(acc[i][j][3] * 0.01f, 0.f));
            *reinterpret_cast<uint32_t*>(sm + r0 * 144 + col * 2)       = h0;
            *reinterpret_cast<uint32_t*>(sm + (r0 + 8) * 144 + col * 2) = h1;
        }
    __syncthreads();

    #pragma unroll
    for (int i = 0; i < 4; i++)
        #pragma unroll
        for (int j = 0; j < 4; j++)
            #pragma unroll
            for (int r = 0; r < 4; r++) acc[i][j][r] = 0.f;

    #pragma unroll
    for (int ks = 0; ks < 4; ks++) {
        uint32_t a[4][4], bb[2][4];
        #pragma unroll
        for (int i = 0; i < 4; i++)
            ldsm4(a[i], sb + (wm * 64 + i * 16 + (lane & 15)) * 144
                        + ks * 32 + (lane >> 4) * 16);
        #pragma unroll
        for (int p = 0; p < 2; p++)
            ldsm4t(bb[p], sb + F_W + (ks * 16 + (lane & 15)) * 144
                          + (wn * 32 + p * 16 + (lane >> 4) * 8) * 2);
        #pragma unroll
        for (int j = 0; j < 4; j++) {
            uint32_t b0 = bb[j >> 1][(j & 1) * 2];
            uint32_t b1 = bb[j >> 1][(j & 1) * 2 + 1];
            #pragma unroll
            for (int i = 0; i < 4; i++) mma16(acc[i][j], a[i], b0, b1);
        }
    }

    const float* mrow = nmask + (size_t)b * NP;
    #pragma unroll
    for (int j = 0; j < 4; j++) {
        int col = wn * 32 + j * 8 + 2 * t;
        float b0 = bias[col], b1 = bias[col + 1];
        #pragma unroll
        for (int i = 0; i < 4; i++) {
            int r0 = wm * 64 + i * 16 + g;
            float m0 = mrow[r0], m1 = mrow[r0 + 8];
            float2 v0, v1;
            v0.x = (acc[i][j][0] + b0) * m0;
            v0.y = (acc[i][j][1] + b1) * m0;
            v1.x = (acc[i][j][2] + b0) * m1;
            v1.y = (acc[i][j][3] + b1) * m1;
            *reinterpret_cast<float2*>(out + ((size_t)b * NP + r0) * HD + col)     = v0;
            *reinterpret_cast<float2*>(out + ((size_t)b * NP + r0 + 8) * HD + col) = v1;
        }
    }
}

// ---------------------------------------------------------------------------
extern "C" void kernel_launch(void* const* d_in, const int* in_sizes, int n_in,
                              void* d_out, int out_size) {
    const float* x       = (const float*)d_in[0];
    const float* adj     = (const float*)d_in[1];
    const float* nmask   = (const float*)d_in[2];
    const float* W_embed = (const float*)d_in[3];
    const float* W0      = (const float*)d_in[4];
    const float* b0      = (const float*)d_in[5];
    const float* W1      = (const float*)d_in[6];
    const float* b1      = (const float*)d_in[7];
    const float* W_out   = (const float*)d_in[8];
    const float* b_out   = (const float*)d_in[9];
    float* out = (float*)d_out;

    __half *bufA = nullptr, *bufB = nullptr, *adjh = nullptr;
    uint16_t* wpre = nullptr;
    cudaGetSymbolAddress((void**)&bufA, g_bufA);
    cudaGetSymbolAddress((void**)&bufB, g_bufB);
    cudaGetSymbolAddress((void**)&adjh, g_adjh);
    cudaGetSymbolAddress((void**)&wpre, g_WpreH);

    cudaFuncSetAttribute(kRowH, cudaFuncAttributeMaxDynamicSharedMemorySize, KR_BYTES);
    cudaFuncSetAttribute(kAdjC, cudaFuncAttributeMaxDynamicSharedMemorySize, C_BYTES);
    cudaFuncSetAttribute(kAdjF, cudaFuncAttributeMaxDynamicSharedMemorySize, F_BYTES);

    kPrep<<<160, 256>>>(W_embed, W0, W1, W_out, wpre);
    kRowH<<<1024, 256, KR_BYTES>>>(x, wpre, b0, bufA);
    kAdjC<<<512, 256, C_BYTES>>>(adj, bufA, wpre + 4096, b1, bufB, adjh);
    kAdjF<<<512, 256, F_BYTES>>>(adjh, bufB, wpre + 8192, b_out, nmask, out);
}

// round 16
// speedup vs baseline: 1.1737x; 1.0670x over previous
#include <cuda_runtime.h>
#include <cuda_fp16.h>
#include <cstdint>

// HGCN (math-reduced), fp16 mma.sync — R15 pipeline with restructured kAdj
// mainloops: 1 barrier/chunk (cp.async self-visibility for the convert),
// cp.async.cg direct-to-smem for all streamed tiles (L1 bypass), no
// register-held staging.
//   kPrep : W01h=half(We@W0z); W1zh/Wozh=half(row0-zeroed W1/W_out)  [k][n]
//   kRowH : S0 = half(x @ W01 + b0)                  (row-major half)
//   kAdjC : S1 = half(relu(adj@S0/100) @ W1z + b1); also writes adj_h=half(adj)
//   kAdjF : out = (relu(adj_h@S1/100) @ Woz + b_out) * mask   (fp32)
// m16n8k16 HMMA fp32-accum; A via ldmatrix.x4 (64B swizzled rows), B/W/T via
// ldmatrix.x4.trans (144B pitch). kAdj: 256 threads, warp tile m64n32.

static constexpr int NP = 256, HD = 64;

__device__ __half   g_bufA[131072 * 64];     // S0
__device__ __half   g_bufB[131072 * 64];     // S1
__device__ __half   g_adjh[512 * 256 * 256]; // half adj (written by kAdjC)
__device__ uint16_t g_WpreH[3 * 4096];

// ---- kAdjC smem (bytes) ----------------------------------------------------
static constexpr int C_ST = 0;        // fp32 adj stage 256x128B = 32768
static constexpr int C_A0 = 32768;    // half A tile 256x64B (swizzled)
static constexpr int C_A1 = 49152;
static constexpr int C_B0 = 65536;    // S chunk 32x144B = 4608
static constexpr int C_B1 = 70144;
static constexpr int C_W  = 74752;    // 64x144B = 9216
static constexpr int C_BYTES = 83968; // T tile (36864B) overlays offset 0
// ---- kAdjF smem ------------------------------------------------------------
static constexpr int F_A0 = 0;
static constexpr int F_A1 = 16384;
static constexpr int F_B0 = 32768;
static constexpr int F_B1 = 37376;
static constexpr int F_W  = 41984;
static constexpr int F_BYTES = 51200;
// ---- kRowH smem ------------------------------------------------------------
static constexpr int KR_ST   = 0;
static constexpr int KR_XH   = 32768;
static constexpr int KR_W    = 51200;
static constexpr int KR_BIAS = 60416;
static constexpr int KR_BYTES= 60672;

// ---- helpers ---------------------------------------------------------------
__device__ __forceinline__ uint32_t smem_u32(const void* p) {
    uint32_t a;
    asm("{ .reg .u64 t; cvta.to.shared.u64 t, %1; cvt.u32.u64 %0, t; }"
        : "=r"(a) : "l"(p));
    return a;
}
__device__ __forceinline__ void cpa16(uint32_t dst, const void* src) {
    asm volatile("cp.async.ca.shared.global [%0], [%1], 16;\n"
                 :: "r"(dst), "l"(src));
}
// L1-bypass variant for streamed (consume-once) tiles
__device__ __forceinline__ void cpa16cg(uint32_t dst, const void* src) {
    asm volatile("cp.async.cg.shared.global [%0], [%1], 16;\n"
                 :: "r"(dst), "l"(src));
}
__device__ __forceinline__ void ldsm4(uint32_t* r, uint32_t addr) {
    asm volatile("ldmatrix.sync.aligned.m8n8.x4.shared.b16 {%0,%1,%2,%3}, [%4];"
                 : "=r"(r[0]), "=r"(r[1]), "=r"(r[2]), "=r"(r[3]) : "r"(addr));
}
__device__ __forceinline__ void ldsm4t(uint32_t* r, uint32_t addr) {
    asm volatile("ldmatrix.sync.aligned.m8n8.x4.trans.shared.b16 {%0,%1,%2,%3}, [%4];"
                 : "=r"(r[0]), "=r"(r[1]), "=r"(r[2]), "=r"(r[3]) : "r"(addr));
}
__device__ __forceinline__ void mma16(float* c, const uint32_t* a,
                                      uint32_t b0, uint32_t b1) {
    asm volatile(
        "mma.sync.aligned.m16n8k16.row.col.f32.f16.f16.f32 "
        "{%0,%1,%2,%3}, {%4,%5,%6,%7}, {%8,%9}, {%0,%1,%2,%3};\n"
        : "+f"(c[0]), "+f"(c[1]), "+f"(c[2]), "+f"(c[3])
        : "r"(a[0]), "r"(a[1]), "r"(a[2]), "r"(a[3]), "r"(b0), "r"(b1));
}
__device__ __forceinline__ uint32_t pk2h(float a, float b) {
    __half2 h = __floats2half2_rn(a, b);
    return *reinterpret_cast<uint32_t*>(&h);
}
// A-tile swizzle: 64B rows, 16B units; unit' = q ^ ((r>>1)&3)
__device__ __forceinline__ int aswz(int r, int q) {
    return r * 64 + ((q ^ ((r >> 1) & 3)) << 4);
}

// ---------------------------------------------------------------------------
// kPrep (parallel): blocks 0..127: W01 = half(We@W0z), 8-way K-split + shfl.
// blocks 128..159: W1z / Woz row0-zeroed converts.
// ---------------------------------------------------------------------------
__global__ void __launch_bounds__(256)
kPrep(const float* __restrict__ We, const float* __restrict__ W0,
      const float* __restrict__ W1, const float* __restrict__ Wo,
      uint16_t* __restrict__ WpreH) {
    const int blk = blockIdx.x, tid = threadIdx.x;
    if (blk < 128) {
        int out = blk * 32 + (tid >> 3);
        int r = out >> 6, c = out & 63;
        int l8 = tid & 7;
        float s = 0.f;
        #pragma unroll
        for (int m = 0; m < 8; m++) {
            int k = l8 * 8 + m;
            if (k != 0) s += We[r * 64 + k] * W0[k * 64 + c];
        }
        s += __shfl_down_sync(0xffffffffu, s, 4, 8);
        s += __shfl_down_sync(0xffffffffu, s, 2, 8);
        s += __shfl_down_sync(0xffffffffu, s, 1, 8);
        if (l8 == 0) {
            __half h = __float2half_rn(s);
            WpreH[out] = *reinterpret_cast<uint16_t*>(&h);
        }
    } else {
        int id = (blk - 128) * 256 + tid;
        int which = 1 + (id >> 12);
        int li = id & 4095;
        int k = li >> 6;
        const float* W = (which == 1) ? W1 : Wo;
        float v = (k == 0) ? 0.f : W[li];
        __half h = __float2half_rn(v);
        WpreH[which * 4096 + li] = *reinterpret_cast<uint16_t*>(&h);
    }
}

// ---------------------------------------------------------------------------
// kRowH (R15 verbatim): S0 = half(x @ W01 + b0)
// ---------------------------------------------------------------------------
__global__ void __launch_bounds__(256, 2)
kRowH(const float* __restrict__ X, const uint16_t* __restrict__ Wh,
      const float* __restrict__ bias, __half* __restrict__ S) {
    extern __shared__ char sm[];
    const uint32_t sb = smem_u32(sm);
    const int tid = threadIdx.x;
    const int lane = tid & 31, w = tid >> 5;
    const int g = lane >> 2;
    const int wm = w & 3, wn = w >> 2;
    const long row0 = (long)blockIdx.x * 128;

    #pragma unroll
    for (int i = 0; i < 8; i++) {
        int u = tid + i * 256;
        cpa16cg(sb + KR_ST + u * 16, X + (row0 + (u >> 4)) * 64 + (u & 15) * 4);
    }
    #pragma unroll
    for (int i = 0; i < 2; i++) {
        int u = tid + i * 256;
        cpa16(sb + KR_W + (u >> 3) * 144 + (u & 7) * 16,
              Wh + (u >> 3) * 64 + (u & 7) * 8);
    }
    asm volatile("cp.async.commit_group;\n");
    if (tid < HD) *reinterpret_cast<float*>(sm + KR_BIAS + tid * 4) = bias[tid];
    asm volatile("cp.async.wait_group 0;\n");
    __syncthreads();

    #pragma unroll
    for (int i = 0; i < 8; i++) {
        int u = tid + i * 256;
        int r = u >> 4, q = u & 15;
        float4 v = *reinterpret_cast<float4*>(sm + KR_ST + u * 16);
        uint2 h;
        h.x = pk2h(v.x, v.y);
        h.y = pk2h(v.z, v.w);
        *reinterpret_cast<uint2*>(sm + KR_XH + r * 144 + q * 8) = h;
    }
    __syncthreads();

    float acc[2][4][4];
    #pragma unroll
    for (int i = 0; i < 2; i++)
        #pragma unroll
        for (int j = 0; j < 4; j++)
            #pragma unroll
            for (int r = 0; r < 4; r++) acc[i][j][r] = 0.f;

    #pragma unroll
    for (int ks = 0; ks < 4; ks++) {
        uint32_t a[2][4], bb[2][4];
        #pragma unroll
        for (int i = 0; i < 2; i++)
            ldsm4(a[i], sb + KR_XH + (wm * 32 + i * 16 + (lane & 15)) * 144
                        + ks * 32 + (lane >> 4) * 16);
        #pragma unroll
        for (int p = 0; p < 2; p++)
            ldsm4t(bb[p], sb + KR_W + (ks * 16 + (lane & 15)) * 144
                          + (wn * 32 + p * 16 + (lane >> 4) * 8) * 2);
        #pragma unroll
        for (int j = 0; j < 4; j++) {
            uint32_t b0 = bb[j >> 1][(j & 1) * 2];
            uint32_t b1 = bb[j >> 1][(j & 1) * 2 + 1];
            mma16(acc[0][j], a[0], b0, b1);
            mma16(acc[1][j], a[1], b0, b1);
        }
    }

    const float* bsm = reinterpret_cast<const float*>(sm + KR_BIAS);
    #pragma unroll
    for (int i = 0; i < 2; i++)
        #pragma unroll
        for (int j = 0; j < 4; j++) {
            int col = wn * 32 + j * 8 + 2 * (lane & 3);
            float b0 = bsm[col], b1 = bsm[col + 1];
            int r0 = wm * 32 + i * 16 + g;
            uint32_t h0 = pk2h(acc[i][j][0] + b0, acc[i][j][1] + b1);
            uint32_t h1 = pk2h(acc[i][j][2] + b0, acc[i][j][3] + b1);
            *reinterpret_cast<uint32_t*>(S + (row0 + r0) * 64 + col)     = h0;
            *reinterpret_cast<uint32_t*>(S + (row0 + r0 + 8) * 64 + col) = h1;
        }
}

// ---------------------------------------------------------------------------
// kAdjC: fp32 adj in; writes S1 + adj_h. ONE barrier per chunk: the fp32->
// half convert reads exactly the bytes this thread cp.async'd (wait_group
// makes own copies visible without a CTA barrier). B chunks via cp.async.cg.
// ---------------------------------------------------------------------------
__global__ void __launch_bounds__(256, 2)
kAdjC(const float* __restrict__ adj, const __half* __restrict__ S,
      const uint16_t* __restrict__ Wh, const float* __restrict__ bias,
      __half* __restrict__ S1, __half* __restrict__ adjh) {
    extern __shared__ char sm[];
    const uint32_t sb = smem_u32(sm);
    const int tid = threadIdx.x;
    const int lane = tid & 31, w = tid >> 5;
    const int g = lane >> 2, t = lane & 3;
    const int wm = w & 3, wn = w >> 2;
    const int b = blockIdx.x;

    const float*  adjb  = adj + (size_t)b * NP * NP;
    const __half* Sb    = S + (size_t)b * NP * HD;
    __half*       adjhb = adjh + (size_t)b * NP * NP;

    auto stageA = [&](int c) {      // fp32 adj chunk -> single stage buffer
        #pragma unroll
        for (int i = 0; i < 8; i++) {
            int u = tid + i * 256;
            cpa16cg(sb + C_ST + u * 16,
                    adjb + (size_t)(u >> 3) * NP + c * 32 + (u & 7) * 4);
        }
    };
    auto stageB = [&](int c) {      // S chunk -> BH(c&1)
        int r = tid >> 3, q = tid & 7;   // 32 rows x 8 units
        cpa16cg(sb + ((c & 1) ? C_B1 : C_B0) + r * 144 + q * 16,
                Sb + (size_t)(c * 32 + r) * HD + q * 8);
    };

    // prologue: W + stage(0) + B(0), one group
    #pragma unroll
    for (int i = 0; i < 2; i++) {
        int u = tid + i * 256;
        cpa16(sb + C_W + (u >> 3) * 144 + (u & 7) * 16,
              Wh + (u >> 3) * 64 + (u & 7) * 8);
    }
    stageA(0);
    stageB(0);
    asm volatile("cp.async.commit_group;\n");

    float acc[4][4][4];
    #pragma unroll
    for (int i = 0; i < 4; i++)
        #pragma unroll
        for (int j = 0; j < 4; j++)
            #pragma unroll
            for (int r = 0; r < 4; r++) acc[i][j][r] = 0.f;

    for (int c = 0; c < 8; c++) {
        asm volatile("cp.async.wait_group 0;\n");   // own stage bytes visible

        // convert own staged fp32 -> AH(c&1) + global adj_h (no barrier needed)
        const int AH = (c & 1) ? C_A1 : C_A0;
        #pragma unroll
        for (int i = 0; i < 8; i++) {
            int u = tid + i * 256;
            int r = u >> 3, q32 = u & 7;
            float4 v = *reinterpret_cast<float4*>(sm + C_ST + u * 16);
            uint2 h;
            h.x = pk2h(v.x, v.y);
            h.y = pk2h(v.z, v.w);
            *reinterpret_cast<uint2*>(sm + AH + aswz(r, q32 >> 1) + (q32 & 1) * 8) = h;
            *reinterpret_cast<uint2*>(adjhb + (size_t)r * NP + c * 32 + q32 * 4) = h;
        }
        __syncthreads();            // AH/B(c) CTA-visible; stage fully consumed

        if (c + 1 < 8) {            // refill stage + B(c+1); overlaps mma below
            stageA(c + 1);
            stageB(c + 1);
            asm volatile("cp.async.commit_group;\n");
        }

        const int BH = (c & 1) ? C_B1 : C_B0;
        #pragma unroll
        for (int s = 0; s < 2; s++) {
            uint32_t a[4][4], bb[2][4];
            #pragma unroll
            for (int i = 0; i < 4; i++) {
                int r = wm * 64 + i * 16 + (lane & 15);
                ldsm4(a[i], sb + AH + aswz(r, 2 * s + (lane >> 4)));
            }
            #pragma unroll
            for (int p = 0; p < 2; p++)
                ldsm4t(bb[p], sb + BH + (s * 16 + (lane & 15)) * 144
                              + (wn * 32 + p * 16 + (lane >> 4) * 8) * 2);
            #pragma unroll
            for (int j = 0; j < 4; j++) {
                uint32_t b0 = bb[j >> 1][(j & 1) * 2];
                uint32_t b1 = bb[j >> 1][(j & 1) * 2 + 1];
                #pragma unroll
                for (int i = 0; i < 4; i++) mma16(acc[i][j], a[i], b0, b1);
            }
        }
    }

    __syncthreads();                // everything dead -> T overlay @ 0

    #pragma unroll
    for (int i = 0; i < 4; i++)
        #pragma unroll
        for (int j = 0; j < 4; j++) {
            int r0 = wm * 64 + i * 16 + g;
            int col = wn * 32 + j * 8 + 2 * t;
            uint32_t h0 = pk2h(fmaxf(acc[i][j][0] * 0.01f, 0.f),
                               fmaxf(acc[i][j][1] * 0.01f, 0.f));
            uint32_t h1 = pk2h(fmaxf(acc[i][j][2] * 0.01f, 0.f),
                               fmaxf(acc[i][j][3] * 0.01f, 0.f));
            *reinterpret_cast<uint32_t*>(sm + r0 * 144 + col * 2)       = h0;
            *reinterpret_cast<uint32_t*>(sm + (r0 + 8) * 144 + col * 2) = h1;
        }
    __syncthreads();

    #pragma unroll
    for (int i = 0; i < 4; i++)
        #pragma unroll
        for (int j = 0; j < 4; j++)
            #pragma unroll
            for (int r = 0; r < 4; r++) acc[i][j][r] = 0.f;

    #pragma unroll
    for (int ks = 0; ks < 4; ks++) {
        uint32_t a[4][4], bb[2][4];
        #pragma unroll
        for (int i = 0; i < 4; i++)
            ldsm4(a[i], sb + (wm * 64 + i * 16 + (lane & 15)) * 144
                        + ks * 32 + (lane >> 4) * 16);
        #pragma unroll
        for (int p = 0; p < 2; p++)
            ldsm4t(bb[p], sb + C_W + (ks * 16 + (lane & 15)) * 144
                          + (wn * 32 + p * 16 + (lane >> 4) * 8) * 2);
        #pragma unroll
        for (int j = 0; j < 4; j++) {
            uint32_t b0 = bb[j >> 1][(j & 1) * 2];
            uint32_t b1 = bb[j >> 1][(j & 1) * 2 + 1];
            #pragma unroll
            for (int i = 0; i < 4; i++) mma16(acc[i][j], a[i], b0, b1);
        }
    }

    #pragma unroll
    for (int j = 0; j < 4; j++) {
        int col = wn * 32 + j * 8 + 2 * t;
        float b0 = bias[col], b1 = bias[col + 1];
        #pragma unroll
        for (int i = 0; i < 4; i++) {
            int r0 = wm * 64 + i * 16 + g;
            uint32_t h0 = pk2h(acc[i][j][0] + b0, acc[i][j][1] + b1);
            uint32_t h1 = pk2h(acc[i][j][2] + b0, acc[i][j][3] + b1);
            *reinterpret_cast<uint32_t*>(S1 + ((size_t)b * NP + r0) * HD + col)     = h0;
            *reinterpret_cast<uint32_t*>(S1 + ((size_t)b * NP + r0 + 8) * HD + col) = h1;
        }
    }
}

// ---------------------------------------------------------------------------
// kAdjF: half adj in; A/B chunks via cp.async.cg directly into swizzled smem
// (no register staging, no STS). One barrier per chunk.
// ---------------------------------------------------------------------------
__global__ void __launch_bounds__(256, 2)
kAdjF(const __half* __restrict__ adjh, const __half* __restrict__ S,
      const uint16_t* __restrict__ Wh, const float* __restrict__ bias,
      const float* __restrict__ nmask, float* __restrict__ out) {
    extern __shared__ char sm[];
    const uint32_t sb = smem_u32(sm);
    const int tid = threadIdx.x;
    const int lane = tid & 31, w = tid >> 5;
    const int g = lane >> 2, t = lane & 3;
    const int wm = w & 3, wn = w >> 2;
    const int b = blockIdx.x;

    const __half* adjb = adjh + (size_t)b * NP * NP;
    const __half* Sb   = S + (size_t)b * NP * HD;

    auto prefetch = [&](int c) {
        const int AH = (c & 1) ? F_A1 : F_A0;
        #pragma unroll
        for (int i = 0; i < 4; i++) {          // A: 1024 units, swizzled dst
            int u = tid + i * 256;
            cpa16cg(sb + AH + aswz(u >> 2, u & 3),
                    adjb + (size_t)(u >> 2) * NP + c * 32 + (u & 3) * 8);
        }
        {                                      // B: 256 units
            int r = tid >> 3, q = tid & 7;
            cpa16cg(sb + ((c & 1) ? F_B1 : F_B0) + r * 144 + q * 16,
                    Sb + (size_t)(c * 32 + r) * HD + q * 8);
        }
        asm volatile("cp.async.commit_group;\n");
    };

    // prologue: W group, then chunk-0 group
    #pragma unroll
    for (int i = 0; i < 2; i++) {
        int u = tid + i * 256;
        cpa16(sb + F_W + (u >> 3) * 144 + (u & 7) * 16,
              Wh + (u >> 3) * 64 + (u & 7) * 8);
    }
    asm volatile("cp.async.commit_group;\n");
    prefetch(0);

    float acc[4][4][4];
    #pragma unroll
    for (int i = 0; i < 4; i++)
        #pragma unroll
        for (int j = 0; j < 4; j++)
            #pragma unroll
            for (int r = 0; r < 4; r++) acc[i][j][r] = 0.f;

    for (int c = 0; c < 8; c++) {
        asm volatile("cp.async.wait_group 0;\n");   // chunk c landed
        __syncthreads();                            // CTA-visible; mma(c-1) done
        if (c + 1 < 8) prefetch(c + 1);             // overlaps mma(c)

        const int AH = (c & 1) ? F_A1 : F_A0;
        const int BH = (c & 1) ? F_B1 : F_B0;
        #pragma unroll
        for (int s = 0; s < 2; s++) {
            uint32_t a[4][4], bb[2][4];
            #pragma unroll
            for (int i = 0; i < 4; i++) {
                int r = wm * 64 + i * 16 + (lane & 15);
                ldsm4(a[i], sb + AH + aswz(r, 2 * s + (lane >> 4)));
            }
            #pragma unroll
            for (int p = 0; p < 2; p++)
                ldsm4t(bb[p], sb + BH + (s * 16 + (lane & 15)) * 144
                              + (wn * 32 + p * 16 + (lane >> 4) * 8) * 2);
            #pragma unroll
            for (int j = 0; j < 4; j++) {
                uint32_t b0 = bb[j >> 1][(j & 1) * 2];
                uint32_t b1 = bb[j >> 1][(j & 1) * 2 + 1];
                #pragma unroll
                for (int i = 0; i < 4; i++) mma16(acc[i][j], a[i], b0, b1);
            }
        }
    }

    __syncthreads();                // tiles dead -> T overlay

    #pragma unroll
    for (int i = 0; i < 4; i++)
        #pragma unroll
        for (int j = 0; j < 4; j++) {
            int r0 = wm * 64 + i * 16 + g;
            int col = wn * 32 + j * 8 + 2 * t;
            uint32_t h0 = pk2h(fmaxf(acc[i][j][0] * 0.01f, 0.f),
                               fmaxf(acc[i][j][1] * 0.01f, 0.f));
            uint32_t h1 = pk2h(fmaxf(acc[i][j][2] * 0.01f, 0.f),
                               fmaxf(acc[i][j][3] * 0.01f, 0.f));
            *reinterpret_cast<uint32_t*>(sm + r0 * 144 + col * 2)       = h0;
            *reinterpret_cast<uint32_t*>(sm + (r0 + 8) * 144 + col * 2) = h1;
        }
    __syncthreads();

    #pragma unroll
    for (int i = 0; i < 4; i++)
        #pragma unroll
        for (int j = 0; j < 4; j++)
            #pragma unroll
            for (int r = 0; r < 4; r++) acc[i][j][r] = 0.f;

    #pragma unroll
    for (int ks = 0; ks < 4; ks++) {
        uint32_t a[4][4], bb[2][4];
        #pragma unroll
        for (int i = 0; i < 4; i++)
            ldsm4(a[i], sb + (wm * 64 + i * 16 + (lane & 15)) * 144
                        + ks * 32 + (lane >> 4) * 16);
        #pragma unroll
        for (int p = 0; p < 2; p++)
            ldsm4t(bb[p], sb + F_W + (ks * 16 + (lane & 15)) * 144
                          + (wn * 32 + p * 16 + (lane >> 4) * 8) * 2);
        #pragma unroll
        for (int j = 0; j < 4; j++) {
            uint32_t b0 = bb[j >> 1][(j & 1) * 2];
            uint32_t b1 = bb[j >> 1][(j & 1) * 2 + 1];
            #pragma unroll
            for (int i = 0; i < 4; i++) mma16(acc[i][j], a[i], b0, b1);
        }
    }

    const float* mrow = nmask + (size_t)b * NP;
    #pragma unroll
    for (int j = 0; j < 4; j++) {
        int col = wn * 32 + j * 8 + 2 * t;
        float b0 = bias[col], b1 = bias[col + 1];
        #pragma unroll
        for (int i = 0; i < 4; i++) {
            int r0 = wm * 64 + i * 16 + g;
            float m0 = mrow[r0], m1 = mrow[r0 + 8];
            float2 v0, v1;
            v0.x = (acc[i][j][0] + b0) * m0;
            v0.y = (acc[i][j][1] + b1) * m0;
            v1.x = (acc[i][j][2] + b0) * m1;
            v1.y = (acc[i][j][3] + b1) * m1;
            *reinterpret_cast<float2*>(out + ((size_t)b * NP + r0) * HD + col)     = v0;
            *reinterpret_cast<float2*>(out + ((size_t)b * NP + r0 + 8) * HD + col) = v1;
        }
    }
}

// ---------------------------------------------------------------------------
extern "C" void kernel_launch(void* const* d_in, const int* in_sizes, int n_in,
                              void* d_out, int out_size) {
    const float* x       = (const float*)d_in[0];
    const float* adj     = (const float*)d_in[1];
    const float* nmask   = (const float*)d_in[2];
    const float* W_embed = (const float*)d_in[3];
    const float* W0      = (const float*)d_in[4];
    const float* b0      = (const float*)d_in[5];
    const float* W1      = (const float*)d_in[6];
    const float* b1      = (const float*)d_in[7];
    const float* W_out   = (const float*)d_in[8];
    const float* b_out   = (const float*)d_in[9];
    float* out = (float*)d_out;

    __half *bufA = nullptr, *bufB = nullptr, *adjh = nullptr;
    uint16_t* wpre = nullptr;
    cudaGetSymbolAddress((void**)&bufA, g_bufA);
    cudaGetSymbolAddress((void**)&bufB, g_bufB);
    cudaGetSymbolAddress((void**)&adjh, g_adjh);
    cudaGetSymbolAddress((void**)&wpre, g_WpreH);

    cudaFuncSetAttribute(kRowH, cudaFuncAttributeMaxDynamicSharedMemorySize, KR_BYTES);
    cudaFuncSetAttribute(kAdjC, cudaFuncAttributeMaxDynamicSharedMemorySize, C_BYTES);
    cudaFuncSetAttribute(kAdjF, cudaFuncAttributeMaxDynamicSharedMemorySize, F_BYTES);

    kPrep<<<160, 256>>>(W_embed, W0, W1, W_out, wpre);
    kRowH<<<1024, 256, KR_BYTES>>>(x, wpre, b0, bufA);
    kAdjC<<<512, 256, C_BYTES>>>(adj, bufA, wpre + 4096, b1, bufB, adjh);
    kAdjF<<<512, 256, F_BYTES>>>(adjh, bufB, wpre + 8192, b_out, nmask, out);
}

// round 17
// speedup vs baseline: 1.2496x; 1.0646x over previous
#include <cuda_runtime.h>
#include <cuda_fp16.h>
#include <cstdint>

// HGCN (math-reduced), fp16 mma.sync — R16 pipeline with distance-2 cp.async
// pipelines in both kAdj kernels:
//   kAdjC: double-buffered fp32 adj stage (W tile loaded into the dead ST0
//          region at chunk 6); S chunks via register pipeline.
//   kAdjF: triple-buffered A/B tiles, prefetch distance 2.
//   kPrep : W01h=half(We@W0z); W1zh/Wozh=half(row0-zeroed W1/W_out)  [k][n]
//   kRowH : S0 = half(x @ W01 + b0)                  (row-major half)
//   kAdjC : S1 = half(relu(adj@S0/100) @ W1z + b1); also writes adj_h
//   kAdjF : out = (relu(adj_h@S1/100) @ Woz + b_out) * mask   (fp32)
// m16n8k16 HMMA fp32-accum; A via ldmatrix.x4 (64B swizzled rows), B/W/T via
// ldmatrix.x4.trans (144B pitch). kAdj: 256 threads, warp tile m64n32.

static constexpr int NP = 256, HD = 64;

__device__ __half   g_bufA[131072 * 64];     // S0
__device__ __half   g_bufB[131072 * 64];     // S1
__device__ __half   g_adjh[512 * 256 * 256]; // half adj (written by kAdjC)
__device__ uint16_t g_WpreH[3 * 4096];

// ---- kAdjC smem (bytes) ----------------------------------------------------
static constexpr int C_ST0 = 0;        // fp32 adj stage ring: 2 x 32768
static constexpr int C_ST1 = 32768;
static constexpr int C_A0  = 65536;    // half A tiles (swizzled 64B rows)
static constexpr int C_A1  = 81920;
static constexpr int C_B0  = 98304;    // S chunks 32x144B
static constexpr int C_B1  = 102912;
static constexpr int C_WT  = 0;        // W tile -> dead ST0 region (chunk>=7)
static constexpr int C_T   = 32768;    // T tile overlays ST1+A0 post-mainloop
static constexpr int C_BYTES = 107520; // 2 CTAs/SM
// ---- kAdjF smem ------------------------------------------------------------
static constexpr int F_A0 = 0;         // 3-deep A ring, 16384 each
static constexpr int F_B0 = 49152;     // 3-deep B ring, 4608 each
static constexpr int F_W  = 62976;
static constexpr int F_BYTES = 72192;  // T tile (36864) overlays ring
// ---- kRowH smem ------------------------------------------------------------
static constexpr int KR_ST   = 0;
static constexpr int KR_XH   = 32768;
static constexpr int KR_W    = 51200;
static constexpr int KR_BIAS = 60416;
static constexpr int KR_BYTES= 60672;

// ---- helpers ---------------------------------------------------------------
__device__ __forceinline__ uint32_t smem_u32(const void* p) {
    uint32_t a;
    asm("{ .reg .u64 t; cvta.to.shared.u64 t, %1; cvt.u32.u64 %0, t; }"
        : "=r"(a) : "l"(p));
    return a;
}
__device__ __forceinline__ void cpa16(uint32_t dst, const void* src) {
    asm volatile("cp.async.ca.shared.global [%0], [%1], 16;\n"
                 :: "r"(dst), "l"(src));
}
__device__ __forceinline__ void cpa16cg(uint32_t dst, const void* src) {
    asm volatile("cp.async.cg.shared.global [%0], [%1], 16;\n"
                 :: "r"(dst), "l"(src));
}
__device__ __forceinline__ void ldsm4(uint32_t* r, uint32_t addr) {
    asm volatile("ldmatrix.sync.aligned.m8n8.x4.shared.b16 {%0,%1,%2,%3}, [%4];"
                 : "=r"(r[0]), "=r"(r[1]), "=r"(r[2]), "=r"(r[3]) : "r"(addr));
}
__device__ __forceinline__ void ldsm4t(uint32_t* r, uint32_t addr) {
    asm volatile("ldmatrix.sync.aligned.m8n8.x4.trans.shared.b16 {%0,%1,%2,%3}, [%4];"
                 : "=r"(r[0]), "=r"(r[1]), "=r"(r[2]), "=r"(r[3]) : "r"(addr));
}
__device__ __forceinline__ void mma16(float* c, const uint32_t* a,
                                      uint32_t b0, uint32_t b1) {
    asm volatile(
        "mma.sync.aligned.m16n8k16.row.col.f32.f16.f16.f32 "
        "{%0,%1,%2,%3}, {%4,%5,%6,%7}, {%8,%9}, {%0,%1,%2,%3};\n"
        : "+f"(c[0]), "+f"(c[1]), "+f"(c[2]), "+f"(c[3])
        : "r"(a[0]), "r"(a[1]), "r"(a[2]), "r"(a[3]), "r"(b0), "r"(b1));
}
__device__ __forceinline__ uint32_t pk2h(float a, float b) {
    __half2 h = __floats2half2_rn(a, b);
    return *reinterpret_cast<uint32_t*>(&h);
}
// A-tile swizzle: 64B rows, 16B units; unit' = q ^ ((r>>1)&3)
__device__ __forceinline__ int aswz(int r, int q) {
    return r * 64 + ((q ^ ((r >> 1) & 3)) << 4);
}

// ---------------------------------------------------------------------------
// kPrep (parallel): blocks 0..127: W01 = half(We@W0z), 8-way K-split + shfl.
// blocks 128..159: W1z / Woz row0-zeroed converts.
// ---------------------------------------------------------------------------
__global__ void __launch_bounds__(256)
kPrep(const float* __restrict__ We, const float* __restrict__ W0,
      const float* __restrict__ W1, const float* __restrict__ Wo,
      uint16_t* __restrict__ WpreH) {
    const int blk = blockIdx.x, tid = threadIdx.x;
    if (blk < 128) {
        int out = blk * 32 + (tid >> 3);
        int r = out >> 6, c = out & 63;
        int l8 = tid & 7;
        float s = 0.f;
        #pragma unroll
        for (int m = 0; m < 8; m++) {
            int k = l8 * 8 + m;
            if (k != 0) s += We[r * 64 + k] * W0[k * 64 + c];
        }
        s += __shfl_down_sync(0xffffffffu, s, 4, 8);
        s += __shfl_down_sync(0xffffffffu, s, 2, 8);
        s += __shfl_down_sync(0xffffffffu, s, 1, 8);
        if (l8 == 0) {
            __half h = __float2half_rn(s);
            WpreH[out] = *reinterpret_cast<uint16_t*>(&h);
        }
    } else {
        int id = (blk - 128) * 256 + tid;
        int which = 1 + (id >> 12);
        int li = id & 4095;
        int k = li >> 6;
        const float* W = (which == 1) ? W1 : Wo;
        float v = (k == 0) ? 0.f : W[li];
        __half h = __float2half_rn(v);
        WpreH[which * 4096 + li] = *reinterpret_cast<uint16_t*>(&h);
    }
}

// ---------------------------------------------------------------------------
// kRowH (R16 verbatim): S0 = half(x @ W01 + b0)
// ---------------------------------------------------------------------------
__global__ void __launch_bounds__(256, 2)
kRowH(const float* __restrict__ X, const uint16_t* __restrict__ Wh,
      const float* __restrict__ bias, __half* __restrict__ S) {
    extern __shared__ char sm[];
    const uint32_t sb = smem_u32(sm);
    const int tid = threadIdx.x;
    const int lane = tid & 31, w = tid >> 5;
    const int g = lane >> 2;
    const int wm = w & 3, wn = w >> 2;
    const long row0 = (long)blockIdx.x * 128;

    #pragma unroll
    for (int i = 0; i < 8; i++) {
        int u = tid + i * 256;
        cpa16cg(sb + KR_ST + u * 16, X + (row0 + (u >> 4)) * 64 + (u & 15) * 4);
    }
    #pragma unroll
    for (int i = 0; i < 2; i++) {
        int u = tid + i * 256;
        cpa16(sb + KR_W + (u >> 3) * 144 + (u & 7) * 16,
              Wh + (u >> 3) * 64 + (u & 7) * 8);
    }
    asm volatile("cp.async.commit_group;\n");
    if (tid < HD) *reinterpret_cast<float*>(sm + KR_BIAS + tid * 4) = bias[tid];
    asm volatile("cp.async.wait_group 0;\n");
    __syncthreads();

    #pragma unroll
    for (int i = 0; i < 8; i++) {
        int u = tid + i * 256;
        int r = u >> 4, q = u & 15;
        float4 v = *reinterpret_cast<float4*>(sm + KR_ST + u * 16);
        uint2 h;
        h.x = pk2h(v.x, v.y);
        h.y = pk2h(v.z, v.w);
        *reinterpret_cast<uint2*>(sm + KR_XH + r * 144 + q * 8) = h;
    }
    __syncthreads();

    float acc[2][4][4];
    #pragma unroll
    for (int i = 0; i < 2; i++)
        #pragma unroll
        for (int j = 0; j < 4; j++)
            #pragma unroll
            for (int r = 0; r < 4; r++) acc[i][j][r] = 0.f;

    #pragma unroll
    for (int ks = 0; ks < 4; ks++) {
        uint32_t a[2][4], bb[2][4];
        #pragma unroll
        for (int i = 0; i < 2; i++)
            ldsm4(a[i], sb + KR_XH + (wm * 32 + i * 16 + (lane & 15)) * 144
                        + ks * 32 + (lane >> 4) * 16);
        #pragma unroll
        for (int p = 0; p < 2; p++)
            ldsm4t(bb[p], sb + KR_W + (ks * 16 + (lane & 15)) * 144
                          + (wn * 32 + p * 16 + (lane >> 4) * 8) * 2);
        #pragma unroll
        for (int j = 0; j < 4; j++) {
            uint32_t b0 = bb[j >> 1][(j & 1) * 2];
            uint32_t b1 = bb[j >> 1][(j & 1) * 2 + 1];
            mma16(acc[0][j], a[0], b0, b1);
            mma16(acc[1][j], a[1], b0, b1);
        }
    }

    const float* bsm = reinterpret_cast<const float*>(sm + KR_BIAS);
    #pragma unroll
    for (int i = 0; i < 2; i++)
        #pragma unroll
        for (int j = 0; j < 4; j++) {
            int col = wn * 32 + j * 8 + 2 * (lane & 3);
            float b0 = bsm[col], b1 = bsm[col + 1];
            int r0 = wm * 32 + i * 16 + g;
            uint32_t h0 = pk2h(acc[i][j][0] + b0, acc[i][j][1] + b1);
            uint32_t h1 = pk2h(acc[i][j][2] + b0, acc[i][j][3] + b1);
            *reinterpret_cast<uint32_t*>(S + (row0 + r0) * 64 + col)     = h0;
            *reinterpret_cast<uint32_t*>(S + (row0 + r0 + 8) * 64 + col) = h1;
        }
}

// ---------------------------------------------------------------------------
// kAdjC: double-buffered fp32 stage (distance-2). Per chunk: wait_group 1
// (stage c resident; c+1 in flight), convert own bytes -> AH + adj_h,
// STS rB, barrier, commit stage(c+2) [or W at c==6], mma.
// ---------------------------------------------------------------------------
__global__ void __launch_bounds__(256, 2)
kAdjC(const float* __restrict__ adj, const __half* __restrict__ S,
      const uint16_t* __restrict__ Wh, const float* __restrict__ bias,
      __half* __restrict__ S1, __half* __restrict__ adjh) {
    extern __shared__ char sm[];
    const uint32_t sb = smem_u32(sm);
    const int tid = threadIdx.x;
    const int lane = tid & 31, w = tid >> 5;
    const int g = lane >> 2, t = lane & 3;
    const int wm = w & 3, wn = w >> 2;
    const int b = blockIdx.x;

    const float*  adjb  = adj + (size_t)b * NP * NP;
    const __half* Sb    = S + (size_t)b * NP * HD;
    __half*       adjhb = adjh + (size_t)b * NP * NP;

    auto stageA = [&](int c) {      // fp32 adj chunk -> ST(c&1), own group
        const int ST = (c & 1) ? C_ST1 : C_ST0;
        #pragma unroll
        for (int i = 0; i < 8; i++) {
            int u = tid + i * 256;
            cpa16cg(sb + ST + u * 16,
                    adjb + (size_t)(u >> 3) * NP + c * 32 + (u & 7) * 4);
        }
        asm volatile("cp.async.commit_group;\n");
    };

    stageA(0);                      // G0
    stageA(1);                      // G1
    uint4 rB = *reinterpret_cast<const uint4*>(
        Sb + (size_t)(tid >> 3) * HD + (tid & 7) * 8);

    float acc[4][4][4];
    #pragma unroll
    for (int i = 0; i < 4; i++)
        #pragma unroll
        for (int j = 0; j < 4; j++)
            #pragma unroll
            for (int r = 0; r < 4; r++) acc[i][j][r] = 0.f;

    for (int c = 0; c < 8; c++) {
        asm volatile("cp.async.wait_group 1;\n");   // stage c resident

        const int ST = (c & 1) ? C_ST1 : C_ST0;
        const int AH = (c & 1) ? C_A1 : C_A0;
        const int BH = (c & 1) ? C_B1 : C_B0;
        // convert own staged fp32 -> AH + global adj_h (self-visible bytes)
        #pragma unroll
        for (int i = 0; i < 8; i++) {
            int u = tid + i * 256;
            int r = u >> 3, q32 = u & 7;
            float4 v = *reinterpret_cast<float4*>(sm + ST + u * 16);
            uint2 h;
            h.x = pk2h(v.x, v.y);
            h.y = pk2h(v.z, v.w);
            *reinterpret_cast<uint2*>(sm + AH + aswz(r, q32 >> 1) + (q32 & 1) * 8) = h;
            *reinterpret_cast<uint2*>(adjhb + (size_t)r * NP + c * 32 + q32 * 4) = h;
        }
        *reinterpret_cast<uint4*>(sm + BH + (tid >> 3) * 144 + (tid & 7) * 16) = rB;
        if (c + 1 < 8)
            rB = *reinterpret_cast<const uint4*>(
                Sb + (size_t)((c + 1) * 32 + (tid >> 3)) * HD + (tid & 7) * 8);
        __syncthreads();            // AH/BH(c) visible; ST(c&1) fully consumed

        if (c + 2 < 8) {
            stageA(c + 2);          // reuses ST(c&1); committed after barrier
        } else if (c == 6) {        // W tile into dead ST0 region (group GW)
            #pragma unroll
            for (int i = 0; i < 2; i++) {
                int u = tid + i * 256;
                cpa16(sb + C_WT + (u >> 3) * 144 + (u & 7) * 16,
                      Wh + (u >> 3) * 64 + (u & 7) * 8);
            }
            asm volatile("cp.async.commit_group;\n");
        }

        #pragma unroll
        for (int s = 0; s < 2; s++) {
            uint32_t a[4][4], bb[2][4];
            #pragma unroll
            for (int i = 0; i < 4; i++) {
                int r = wm * 64 + i * 16 + (lane & 15);
                ldsm4(a[i], sb + AH + aswz(r, 2 * s + (lane >> 4)));
            }
            #pragma unroll
            for (int p = 0; p < 2; p++)
                ldsm4t(bb[p], sb + BH + (s * 16 + (lane & 15)) * 144
                              + (wn * 32 + p * 16 + (lane >> 4) * 8) * 2);
            #pragma unroll
            for (int j = 0; j < 4; j++) {
                uint32_t b0 = bb[j >> 1][(j & 1) * 2];
                uint32_t b1 = bb[j >> 1][(j & 1) * 2 + 1];
                #pragma unroll
                for (int i = 0; i < 4; i++) mma16(acc[i][j], a[i], b0, b1);
            }
        }
    }

    asm volatile("cp.async.wait_group 0;\n");   // W tile resident
    __syncthreads();                // all mma done; ST1/A0 dead -> T overlay

    #pragma unroll
    for (int i = 0; i < 4; i++)
        #pragma unroll
        for (int j = 0; j < 4; j++) {
            int r0 = wm * 64 + i * 16 + g;
            int col = wn * 32 + j * 8 + 2 * t;
            uint32_t h0 = pk2h(fmaxf(acc[i][j][0] * 0.01f, 0.f),
                               fmaxf(acc[i][j][1] * 0.01f, 0.f));
            uint32_t h1 = pk2h(fmaxf(acc[i][j][2] * 0.01f, 0.f),
                               fmaxf(acc[i][j][3] * 0.01f, 0.f));
            *reinterpret_cast<uint32_t*>(sm + C_T + r0 * 144 + col * 2)       = h0;
            *reinterpret_cast<uint32_t*>(sm + C_T + (r0 + 8) * 144 + col * 2) = h1;
        }
    __syncthreads();

    #pragma unroll
    for (int i = 0; i < 4; i++)
        #pragma unroll
        for (int j = 0; j < 4; j++)
            #pragma unroll
            for (int r = 0; r < 4; r++) acc[i][j][r] = 0.f;

    #pragma unroll
    for (int ks = 0; ks < 4; ks++) {
        uint32_t a[4][4], bb[2][4];
        #pragma unroll
        for (int i = 0; i < 4; i++)
            ldsm4(a[i], sb + C_T + (wm * 64 + i * 16 + (lane & 15)) * 144
                        + ks * 32 + (lane >> 4) * 16);
        #pragma unroll
        for (int p = 0; p < 2; p++)
            ldsm4t(bb[p], sb + C_WT + (ks * 16 + (lane & 15)) * 144
                          + (wn * 32 + p * 16 + (lane >> 4) * 8) * 2);
        #pragma unroll
        for (int j = 0; j < 4; j++) {
            uint32_t b0 = bb[j >> 1][(j & 1) * 2];
            uint32_t b1 = bb[j >> 1][(j & 1) * 2 + 1];
            #pragma unroll
            for (int i = 0; i < 4; i++) mma16(acc[i][j], a[i], b0, b1);
        }
    }

    #pragma unroll
    for (int j = 0; j < 4; j++) {
        int col = wn * 32 + j * 8 + 2 * t;
        float b0 = bias[col], b1 = bias[col + 1];
        #pragma unroll
        for (int i = 0; i < 4; i++) {
            int r0 = wm * 64 + i * 16 + g;
            uint32_t h0 = pk2h(acc[i][j][0] + b0, acc[i][j][1] + b1);
            uint32_t h1 = pk2h(acc[i][j][2] + b0, acc[i][j][3] + b1);
            *reinterpret_cast<uint32_t*>(S1 + ((size_t)b * NP + r0) * HD + col)     = h0;
            *reinterpret_cast<uint32_t*>(S1 + ((size_t)b * NP + r0 + 8) * HD + col) = h1;
        }
    }
}

// ---------------------------------------------------------------------------
// kAdjF: triple-buffered (distance-2). Per chunk: wait_group 1 (chunk c in,
// c+1 in flight), barrier, prefetch(c+2), mma(c).
// ---------------------------------------------------------------------------
__global__ void __launch_bounds__(256, 2)
kAdjF(const __half* __restrict__ adjh, const __half* __restrict__ S,
      const uint16_t* __restrict__ Wh, const float* __restrict__ bias,
      const float* __restrict__ nmask, float* __restrict__ out) {
    extern __shared__ char sm[];
    const uint32_t sb = smem_u32(sm);
    const int tid = threadIdx.x;
    const int lane = tid & 31, w = tid >> 5;
    const int g = lane >> 2, t = lane & 3;
    const int wm = w & 3, wn = w >> 2;
    const int b = blockIdx.x;

    const __half* adjb = adjh + (size_t)b * NP * NP;
    const __half* Sb   = S + (size_t)b * NP * HD;

    auto prefetch = [&](int c) {
        const int AH = F_A0 + (c % 3) * 16384;
        const int BH = F_B0 + (c % 3) * 4608;
        #pragma unroll
        for (int i = 0; i < 4; i++) {          // A: 1024 units, swizzled dst
            int u = tid + i * 256;
            cpa16cg(sb + AH + aswz(u >> 2, u & 3),
                    adjb + (size_t)(u >> 2) * NP + c * 32 + (u & 3) * 8);
        }
        {                                      // B: 256 units
            int r = tid >> 3, q = tid & 7;
            cpa16cg(sb + BH + r * 144 + q * 16,
                    Sb + (size_t)(c * 32 + r) * HD + q * 8);
        }
        asm volatile("cp.async.commit_group;\n");
    };

    // prologue: G0 = {W, chunk0}; G1 = {chunk1}
    #pragma unroll
    for (int i = 0; i < 2; i++) {
        int u = tid + i * 256;
        cpa16(sb + F_W + (u >> 3) * 144 + (u & 7) * 16,
              Wh + (u >> 3) * 64 + (u & 7) * 8);
    }
    {
        const int AH = F_A0, BH = F_B0;
        #pragma unroll
        for (int i = 0; i < 4; i++) {
            int u = tid + i * 256;
            cpa16cg(sb + AH + aswz(u >> 2, u & 3),
                    adjb + (size_t)(u >> 2) * NP + (u & 3) * 8);
        }
        int r = tid >> 3, q = tid & 7;
        cpa16cg(sb + BH + r * 144 + q * 16, Sb + (size_t)r * HD + q * 8);
        asm volatile("cp.async.commit_group;\n");
    }
    prefetch(1);

    float acc[4][4][4];
    #pragma unroll
    for (int i = 0; i < 4; i++)
        #pragma unroll
        for (int j = 0; j < 4; j++)
            #pragma unroll
            for (int r = 0; r < 4; r++) acc[i][j][r] = 0.f;

    for (int c = 0; c < 8; c++) {
        if (c < 7) asm volatile("cp.async.wait_group 1;\n");
        else       asm volatile("cp.async.wait_group 0;\n");
        __syncthreads();                       // chunk c visible; mma(c-1) done
        if (c + 2 < 8) prefetch(c + 2);        // slot (c+2)%3, last read mma(c-1)

        const int AH = F_A0 + (c % 3) * 16384;
        const int BH = F_B0 + (c % 3) * 4608;
        #pragma unroll
        for (int s = 0; s < 2; s++) {
            uint32_t a[4][4], bb[2][4];
            #pragma unroll
            for (int i = 0; i < 4; i++) {
                int r = wm * 64 + i * 16 + (lane & 15);
                ldsm4(a[i], sb + AH + aswz(r, 2 * s + (lane >> 4)));
            }
            #pragma unroll
            for (int p = 0; p < 2; p++)
                ldsm4t(bb[p], sb + BH + (s * 16 + (lane & 15)) * 144
                              + (wn * 32 + p * 16 + (lane >> 4) * 8) * 2);
            #pragma unroll
            for (int j = 0; j < 4; j++) {
                uint32_t b0 = bb[j >> 1][(j & 1) * 2];
                uint32_t b1 = bb[j >> 1][(j & 1) * 2 + 1];
                #pragma unroll
                for (int i = 0; i < 4; i++) mma16(acc[i][j], a[i], b0, b1);
            }
        }
    }

    __syncthreads();                // tiles dead -> T overlay

    #pragma unroll
    for (int i = 0; i < 4; i++)
        #pragma unroll
        for (int j = 0; j < 4; j++) {
            int r0 = wm * 64 + i * 16 + g;
            int col = wn * 32 + j * 8 + 2 * t;
            uint32_t h0 = pk2h(fmaxf(acc[i][j][0] * 0.01f, 0.f),
                               fmaxf(acc[i][j][1] * 0.01f, 0.f));
            uint32_t h1 = pk2h(fmaxf(acc[i][j][2] * 0.01f, 0.f),
                               fmaxf(acc[i][j][3] * 0.01f, 0.f));
            *reinterpret_cast<uint32_t*>(sm + r0 * 144 + col * 2)       = h0;
            *reinterpret_cast<uint32_t*>(sm + (r0 + 8) * 144 + col * 2) = h1;
        }
    __syncthreads();

    #pragma unroll
    for (int i = 0; i < 4; i++)
        #pragma unroll
        for (int j = 0; j < 4; j++)
            #pragma unroll
            for (int r = 0; r < 4; r++) acc[i][j][r] = 0.f;

    #pragma unroll
    for (int ks = 0; ks < 4; ks++) {
        uint32_t a[4][4], bb[2][4];
        #pragma unroll
        for (int i = 0; i < 4; i++)
            ldsm4(a[i], sb + (wm * 64 + i * 16 + (lane & 15)) * 144
                        + ks * 32 + (lane >> 4) * 16);
        #pragma unroll
        for (int p = 0; p < 2; p++)
            ldsm4t(bb[p], sb + F_W + (ks * 16 + (lane & 15)) * 144
                          + (wn * 32 + p * 16 + (lane >> 4) * 8) * 2);
        #pragma unroll
        for (int j = 0; j < 4; j++) {
            uint32_t b0 = bb[j >> 1][(j & 1) * 2];
            uint32_t b1 = bb[j >> 1][(j & 1) * 2 + 1];
            #pragma unroll
            for (int i = 0; i < 4; i++) mma16(acc[i][j], a[i], b0, b1);
        }
    }

    const float* mrow = nmask + (size_t)b * NP;
    #pragma unroll
    for (int j = 0; j < 4; j++) {
        int col = wn * 32 + j * 8 + 2 * t;
        float b0 = bias[col], b1 = bias[col + 1];
        #pragma unroll
        for (int i = 0; i < 4; i++) {
            int r0 = wm * 64 + i * 16 + g;
            float m0 = mrow[r0], m1 = mrow[r0 + 8];
            float2 v0, v1;
            v0.x = (acc[i][j][0] + b0) * m0;
            v0.y = (acc[i][j][1] + b1) * m0;
            v1.x = (acc[i][j][2] + b0) * m1;
            v1.y = (acc[i][j][3] + b1) * m1;
            *reinterpret_cast<float2*>(out + ((size_t)b * NP + r0) * HD + col)     = v0;
            *reinterpret_cast<float2*>(out + ((size_t)b * NP + r0 + 8) * HD + col) = v1;
        }
    }
}

// ---------------------------------------------------------------------------
extern "C" void kernel_launch(void* const* d_in, const int* in_sizes, int n_in,
                              void* d_out, int out_size) {
    const float* x       = (const float*)d_in[0];
    const float* adj     = (const float*)d_in[1];
    const float* nmask   = (const float*)d_in[2];
    const float* W_embed = (const float*)d_in[3];
    const float* W0      = (const float*)d_in[4];
    const float* b0      = (const float*)d_in[5];
    const float* W1      = (const float*)d_in[6];
    const float* b1      = (const float*)d_in[7];
    const float* W_out   = (const float*)d_in[8];
    const float* b_out   = (const float*)d_in[9];
    float* out = (float*)d_out;

    __half *bufA = nullptr, *bufB = nullptr, *adjh = nullptr;
    uint16_t* wpre = nullptr;
    cudaGetSymbolAddress((void**)&bufA, g_bufA);
    cudaGetSymbolAddress((void**)&bufB, g_bufB);
    cudaGetSymbolAddress((void**)&adjh, g_adjh);
    cudaGetSymbolAddress((void**)&wpre, g_WpreH);

    cudaFuncSetAttribute(kRowH, cudaFuncAttributeMaxDynamicSharedMemorySize, KR_BYTES);
    cudaFuncSetAttribute(kAdjC, cudaFuncAttributeMaxDynamicSharedMemorySize, C_BYTES);
    cudaFuncSetAttribute(kAdjF, cudaFuncAttributeMaxDynamicSharedMemorySize, F_BYTES);

    kPrep<<<160, 256>>>(W_embed, W0, W1, W_out, wpre);
    kRowH<<<1024, 256, KR_BYTES>>>(x, wpre, b0, bufA);
    kAdjC<<<512, 256, C_BYTES>>>(adj, bufA, wpre + 4096, b1, bufB, adjh);
    kAdjF<<<512, 256, F_BYTES>>>(adjh, bufB, wpre + 8192, b_out, nmask, out);
}